// round 9
// baseline (speedup 1.0000x reference)
#include <cuda_runtime.h>
#include <math.h>

#define S_LEN 4096
#define HID   2048
#define NHEAD 16
#define DHEAD 128

// ---------------- scratch (device globals; no allocations allowed) ----------
__device__ float g_Q[(size_t)S_LEN * HID];
__device__ float g_K[(size_t)S_LEN * HID];
__device__ float g_V[(size_t)S_LEN * HID];
__device__ float g_Ao[(size_t)S_LEN * HID];
__device__ int g_minpos;

// ---------------- min(position_ids)  (JAX demotes int64->int32: read as int)
__global__ void minpos_kernel(const int* __restrict__ pos, int n)
{
    __shared__ int sm[256];
    int v = 0x7fffffff;
    for (int i = threadIdx.x; i < n; i += 256) {
        int p = pos[i];
        v = (p < v) ? p : v;
    }
    sm[threadIdx.x] = v;
    __syncthreads();
    for (int s = 128; s > 0; s >>= 1) {
        if (threadIdx.x < s) {
            int o = sm[threadIdx.x + s];
            if (o < sm[threadIdx.x]) sm[threadIdx.x] = o;
        }
        __syncthreads();
    }
    if (threadIdx.x == 0) g_minpos = sm[0];
}

// ---------------- GEMM: C[M,N] = A[M,K] * B[N,K]^T (both row-major, fp32) ---
// 128x128 tile, BK=8, 256 threads, 8x8 register tile per thread.
__global__ __launch_bounds__(256) void gemm_nt_kernel(
    const float* __restrict__ A, const float* __restrict__ B,
    float* __restrict__ C, int M, int N, int K)
{
    __shared__ float As[8][132];
    __shared__ float Bs[8][132];

    const int t  = threadIdx.x;
    const int m0 = blockIdx.y * 128;
    const int n0 = blockIdx.x * 128;
    const int lr = t >> 1;           // 0..127
    const int lc = (t & 1) * 4;      // 0 or 4
    const int ty = t >> 4;           // 0..15
    const int tx = t & 15;           // 0..15

    const float* Ap = A + (size_t)(m0 + lr) * K + lc;
    const float* Bp = B + (size_t)(n0 + lr) * K + lc;

    float acc[8][8];
#pragma unroll
    for (int i = 0; i < 8; i++)
#pragma unroll
        for (int j = 0; j < 8; j++) acc[i][j] = 0.f;

    for (int k0 = 0; k0 < K; k0 += 8) {
        float4 av = *(const float4*)(Ap + k0);
        float4 bv = *(const float4*)(Bp + k0);
        As[lc + 0][lr] = av.x; As[lc + 1][lr] = av.y;
        As[lc + 2][lr] = av.z; As[lc + 3][lr] = av.w;
        Bs[lc + 0][lr] = bv.x; Bs[lc + 1][lr] = bv.y;
        Bs[lc + 2][lr] = bv.z; Bs[lc + 3][lr] = bv.w;
        __syncthreads();

#pragma unroll
        for (int kk = 0; kk < 8; kk++) {
            float a[8], b[8];
            *(float4*)&a[0] = *(const float4*)&As[kk][ty * 8];
            *(float4*)&a[4] = *(const float4*)&As[kk][ty * 8 + 4];
            *(float4*)&b[0] = *(const float4*)&Bs[kk][tx * 8];
            *(float4*)&b[4] = *(const float4*)&Bs[kk][tx * 8 + 4];
#pragma unroll
            for (int i = 0; i < 8; i++)
#pragma unroll
                for (int j = 0; j < 8; j++)
                    acc[i][j] = fmaf(a[i], b[j], acc[i][j]);
        }
        __syncthreads();
    }

#pragma unroll
    for (int i = 0; i < 8; i++) {
        float* cp = C + (size_t)(m0 + ty * 8 + i) * N + n0 + tx * 8;
        *(float4*)cp       = make_float4(acc[i][0], acc[i][1], acc[i][2], acc[i][3]);
        *(float4*)(cp + 4) = make_float4(acc[i][4], acc[i][5], acc[i][6], acc[i][7]);
    }
}

// ---------------- RoPE (LongLlama convention: emb = cat(freqs, freqs)) ------
__global__ void rope_kernel(float* __restrict__ Q, float* __restrict__ K,
                            const int* __restrict__ pos)
{
    int s = blockIdx.x;
    int t = threadIdx.x;          // 1024 threads: (h, d<64)
    int h = t >> 6;
    int d = t & 63;

    float tp = (float)(pos[s] - g_minpos);
    // inv_freq in double, rounded to f32 (matches jax f32 tables to ~0.5 ulp)
    float invf = (float)exp(-log(10000.0) * ((double)(2 * d) / 128.0));
    float ang = tp * invf;        // f32 multiply, same as jnp
    float c, sn;
    sincosf(ang, &sn, &c);

    size_t base = (size_t)s * HID + h * DHEAD;
    float q1 = Q[base + d], q2 = Q[base + d + 64];
    Q[base + d]      = q1 * c - q2 * sn;
    Q[base + d + 64] = q2 * c + q1 * sn;
    float k1 = K[base + d], k2 = K[base + d + 64];
    K[base + d]      = k1 * c - k2 * sn;
    K[base + d + 64] = k2 * c + k1 * sn;
}

// ---------------- flash attention, fp32, causal-block-skipping --------------
// Block: 64 q-rows x full D=128, per (qb, head). 256 threads.
// Score stage: thread (tq,tk) owns q = tq+16i (i<4), k = tk+16j (j<4).
// PV stage:    thread (tq,td=tk) owns q = tq+16i, d = td*8..td*8+7.
// Same row ownership in both stages -> m/l/rescale stay in registers,
// row reductions via half-warp shfl (16 lanes sharing tq are contiguous).
#define QK_STRIDE 132
#define SS_STRIDE 68
#define ATT_SMEM_FLOATS (64 * QK_STRIDE * 2 + 64 * 128 + 64 * SS_STRIDE)

__global__ __launch_bounds__(256) void attn_kernel(
    const float* __restrict__ Q, const float* __restrict__ K,
    const float* __restrict__ V, const float* __restrict__ mask,
    float* __restrict__ O)
{
    extern __shared__ float smf[];
    float* Qs = smf;                      // [64][132]
    float* Ks = Qs + 64 * QK_STRIDE;      // [64][132]
    float* Vs = Ks + 64 * QK_STRIDE;      // [64][128]
    float* Ss = Vs + 64 * 128;            // [64][68]

    const int t  = threadIdx.x;
    const int qb = blockIdx.x;
    const int h  = blockIdx.y;
    const int q0 = qb * 64;
    const int tq = t >> 4;                // 0..15
    const int tk = t & 15;                // 0..15

    // load Q tile (stays resident)
    for (int i = t; i < 64 * 32; i += 256) {
        int r = i >> 5, c = (i & 31) << 2;
        *(float4*)(Qs + r * QK_STRIDE + c) =
            *(const float4*)(Q + (size_t)(q0 + r) * HID + h * DHEAD + c);
    }

    float m_run[4], l_run[4], o[4][8];
#pragma unroll
    for (int i = 0; i < 4; i++) {
        m_run[i] = -INFINITY; l_run[i] = 0.f;
#pragma unroll
        for (int j = 0; j < 8; j++) o[i][j] = 0.f;
    }

    const float scale = 0.08838834764831845f;   // 1/sqrt(128)

    for (int b = 0; b <= qb; b++) {             // causal: skip fully-masked blocks
        const int k0 = b * 64;
        __syncthreads();                        // prev PV done before overwrite
        for (int i = t; i < 64 * 32; i += 256) {
            int r = i >> 5, c = (i & 31) << 2;
            *(float4*)(Ks + r * QK_STRIDE + c) =
                *(const float4*)(K + (size_t)(k0 + r) * HID + h * DHEAD + c);
            *(float4*)(Vs + r * 128 + c) =
                *(const float4*)(V + (size_t)(k0 + r) * HID + h * DHEAD + c);
        }
        __syncthreads();

        // ---- scores: acc[i][j] = Q[tq+16i] . K[tk+16j]
        float acc[4][4];
#pragma unroll
        for (int i = 0; i < 4; i++)
#pragma unroll
            for (int j = 0; j < 4; j++) acc[i][j] = 0.f;

#pragma unroll 8
        for (int d = 0; d < 128; d += 4) {
            float4 qv[4], kv[4];
#pragma unroll
            for (int i = 0; i < 4; i++)
                qv[i] = *(const float4*)(Qs + (tq + 16 * i) * QK_STRIDE + d);
#pragma unroll
            for (int j = 0; j < 4; j++)
                kv[j] = *(const float4*)(Ks + (tk + 16 * j) * QK_STRIDE + d);
#pragma unroll
            for (int i = 0; i < 4; i++)
#pragma unroll
                for (int j = 0; j < 4; j++)
                    acc[i][j] += qv[i].x * kv[j].x + qv[i].y * kv[j].y +
                                 qv[i].z * kv[j].z + qv[i].w * kv[j].w;
        }

        // ---- mask + online softmax (per-row; rows live in one half-warp)
#pragma unroll
        for (int i = 0; i < 4; i++) {
            int q = q0 + tq + 16 * i;
            const float* mrow = mask + (size_t)q * S_LEN + k0;
            float rmax = -INFINITY;
#pragma unroll
            for (int j = 0; j < 4; j++) {
                acc[i][j] = acc[i][j] * scale + mrow[tk + 16 * j];
                rmax = fmaxf(rmax, acc[i][j]);
            }
            rmax = fmaxf(rmax, __shfl_xor_sync(0xffffffffu, rmax, 8));
            rmax = fmaxf(rmax, __shfl_xor_sync(0xffffffffu, rmax, 4));
            rmax = fmaxf(rmax, __shfl_xor_sync(0xffffffffu, rmax, 2));
            rmax = fmaxf(rmax, __shfl_xor_sync(0xffffffffu, rmax, 1));
            float mnew = fmaxf(m_run[i], rmax);
            float fac  = expf(m_run[i] - mnew);
            float rsum = 0.f;
#pragma unroll
            for (int j = 0; j < 4; j++) {
                float p = expf(acc[i][j] - mnew);
                Ss[(tq + 16 * i) * SS_STRIDE + tk + 16 * j] = p;
                rsum += p;
            }
            rsum += __shfl_xor_sync(0xffffffffu, rsum, 8);
            rsum += __shfl_xor_sync(0xffffffffu, rsum, 4);
            rsum += __shfl_xor_sync(0xffffffffu, rsum, 2);
            rsum += __shfl_xor_sync(0xffffffffu, rsum, 1);
            l_run[i] = l_run[i] * fac + rsum;
            m_run[i] = mnew;
#pragma unroll
            for (int j = 0; j < 8; j++) o[i][j] *= fac;
        }
        __syncthreads();

        // ---- PV: o[q][td*8+j] += sum_k P[q][k] * V[k][td*8+j]
#pragma unroll 4
        for (int k = 0; k < 64; k++) {
            float4 v0 = *(const float4*)(Vs + k * 128 + tk * 8);
            float4 v1 = *(const float4*)(Vs + k * 128 + tk * 8 + 4);
#pragma unroll
            for (int i = 0; i < 4; i++) {
                float p = Ss[(tq + 16 * i) * SS_STRIDE + k];
                o[i][0] = fmaf(p, v0.x, o[i][0]);
                o[i][1] = fmaf(p, v0.y, o[i][1]);
                o[i][2] = fmaf(p, v0.z, o[i][2]);
                o[i][3] = fmaf(p, v0.w, o[i][3]);
                o[i][4] = fmaf(p, v1.x, o[i][4]);
                o[i][5] = fmaf(p, v1.y, o[i][5]);
                o[i][6] = fmaf(p, v1.z, o[i][6]);
                o[i][7] = fmaf(p, v1.w, o[i][7]);
            }
        }
    }

    // normalize + write O in [S, HID] layout
#pragma unroll
    for (int i = 0; i < 4; i++) {
        int q = q0 + tq + 16 * i;
        float inv = 1.f / l_run[i];
        float* op = O + (size_t)q * HID + h * DHEAD + tk * 8;
        *(float4*)op = make_float4(o[i][0] * inv, o[i][1] * inv,
                                   o[i][2] * inv, o[i][3] * inv);
        *(float4*)(op + 4) = make_float4(o[i][4] * inv, o[i][5] * inv,
                                         o[i][6] * inv, o[i][7] * inv);
    }
}

// ---------------- launch ----------------------------------------------------
extern "C" void kernel_launch(void* const* d_in, const int* in_sizes, int n_in,
                              void* d_out, int out_size)
{
    const float* X    = (const float*)d_in[0];
    const float* mask = (const float*)d_in[1];
    const int*   pos  = (const int*)d_in[2];   // JAX x64 disabled: int32
    const float* Wq   = (const float*)d_in[3];
    const float* Wk   = (const float*)d_in[4];
    const float* Wv   = (const float*)d_in[5];
    const float* Wo   = (const float*)d_in[6];
    float*       out  = (float*)d_out;

    float *Qp, *Kp, *Vp, *Op;
    cudaGetSymbolAddress((void**)&Qp, g_Q);
    cudaGetSymbolAddress((void**)&Kp, g_K);
    cudaGetSymbolAddress((void**)&Vp, g_V);
    cudaGetSymbolAddress((void**)&Op, g_Ao);

    minpos_kernel<<<1, 256>>>(pos, S_LEN);

    dim3 gg(HID / 128, S_LEN / 128);     // (16, 32)
    gemm_nt_kernel<<<gg, 256>>>(X, Wq, Qp, S_LEN, HID, HID);
    gemm_nt_kernel<<<gg, 256>>>(X, Wk, Kp, S_LEN, HID, HID);
    gemm_nt_kernel<<<gg, 256>>>(X, Wv, Vp, S_LEN, HID, HID);

    rope_kernel<<<S_LEN, 1024>>>(Qp, Kp, pos);

    int smem_bytes = ATT_SMEM_FLOATS * (int)sizeof(float);   // ~117.8 KB
    cudaFuncSetAttribute(attn_kernel,
                         cudaFuncAttributeMaxDynamicSharedMemorySize, smem_bytes);
    dim3 ag(S_LEN / 64, NHEAD);          // (64, 16)
    attn_kernel<<<ag, 256, smem_bytes>>>(Qp, Kp, Vp, mask, Op);

    gemm_nt_kernel<<<gg, 256>>>(Op, Wo, out, S_LEN, HID, HID);
}

// round 11
// speedup vs baseline: 1.6303x; 1.6303x over previous
#include <cuda_runtime.h>
#include <cuda_bf16.h>
#include <math.h>
#include <stdint.h>

#define S_LEN 4096
#define HID   2048
#define NHEAD 16
#define DHEAD 128
#define W_SZ  ((size_t)HID * HID)

// ---------------- scratch (device globals; no allocations allowed) ----------
__device__ float g_Q[(size_t)S_LEN * HID];
__device__ float g_K[(size_t)S_LEN * HID];
__device__ float g_V[(size_t)S_LEN * HID];
__device__ float g_Ao[(size_t)S_LEN * HID];
__device__ __align__(16) __nv_bfloat16 g_Xh[(size_t)S_LEN * HID];
__device__ __align__(16) __nv_bfloat16 g_Xl[(size_t)S_LEN * HID];
__device__ __align__(16) __nv_bfloat16 g_Wh[4 * W_SZ];
__device__ __align__(16) __nv_bfloat16 g_Wl[4 * W_SZ];
__device__ __align__(16) __nv_bfloat16 g_Aoh[(size_t)S_LEN * HID];
__device__ __align__(16) __nv_bfloat16 g_Aol[(size_t)S_LEN * HID];
__device__ int g_minpos;

// ---------------- PTX helpers (all sm_80-era: valid on compute_103) ---------
__device__ __forceinline__ uint32_t smem_u32(const void* p) {
    uint32_t a;
    asm("{ .reg .u64 t; cvta.to.shared.u64 t, %1; cvt.u32.u64 %0, t; }"
        : "=r"(a) : "l"(p));
    return a;
}

__device__ __forceinline__ void cp16(uint32_t saddr, const void* g) {
    asm volatile("cp.async.cg.shared.global [%0], [%1], 16;"
                 :: "r"(saddr), "l"(g) : "memory");
}
__device__ __forceinline__ void cp_commit() {
    asm volatile("cp.async.commit_group;" ::: "memory");
}
template <int N>
__device__ __forceinline__ void cp_wait() {
    asm volatile("cp.async.wait_group %0;" :: "n"(N) : "memory");
}

#define LDSM_X4(r, addr) \
    asm volatile("ldmatrix.sync.aligned.m8n8.x4.shared.b16 {%0,%1,%2,%3}, [%4];" \
                 : "=r"((r)[0]), "=r"((r)[1]), "=r"((r)[2]), "=r"((r)[3]) \
                 : "r"(addr))

__device__ __forceinline__ void mma_bf16(float* c, const uint32_t* a,
                                         uint32_t b0, uint32_t b1) {
    asm volatile(
        "mma.sync.aligned.m16n8k16.row.col.f32.bf16.bf16.f32 "
        "{%0,%1,%2,%3}, {%4,%5,%6,%7}, {%8,%9}, {%0,%1,%2,%3};"
        : "+f"(c[0]), "+f"(c[1]), "+f"(c[2]), "+f"(c[3])
        : "r"(a[0]), "r"(a[1]), "r"(a[2]), "r"(a[3]), "r"(b0), "r"(b1));
}

__device__ __forceinline__ uint32_t swz(uint32_t boff) {   // SW128-style
    return boff ^ ((boff >> 3) & 0x70);
}

// ---------------- min(position_ids)  (JAX demotes int64->int32) -------------
__global__ void minpos_kernel(const int* __restrict__ pos, int n)
{
    __shared__ int sm[256];
    int v = 0x7fffffff;
    for (int i = threadIdx.x; i < n; i += 256) {
        int p = pos[i];
        v = (p < v) ? p : v;
    }
    sm[threadIdx.x] = v;
    __syncthreads();
    for (int s = 128; s > 0; s >>= 1) {
        if (threadIdx.x < s) {
            int o = sm[threadIdx.x + s];
            if (o < sm[threadIdx.x]) sm[threadIdx.x] = o;
        }
        __syncthreads();
    }
    if (threadIdx.x == 0) g_minpos = sm[0];
}

// ---------------- fp32 -> (bf16 hi, bf16 lo) split ---------------------------
__global__ void split_kernel(const float* __restrict__ x,
                             __nv_bfloat16* __restrict__ hi,
                             __nv_bfloat16* __restrict__ lo, int n4)
{
    int i = blockIdx.x * blockDim.x + threadIdx.x;
    if (i >= n4) return;
    float4 v = ((const float4*)x)[i];
    float f[4] = {v.x, v.y, v.z, v.w};
    __nv_bfloat16 h[4], l[4];
#pragma unroll
    for (int j = 0; j < 4; ++j) {
        h[j] = __float2bfloat16(f[j]);
        l[j] = __float2bfloat16(f[j] - __bfloat162float(h[j]));
    }
    ((uint2*)hi)[i] = *(uint2*)h;
    ((uint2*)lo)[i] = *(uint2*)l;
}

// ---------------- mma.sync bf16-split GEMM: C = A * B^T ---------------------
// Tile 128(M) x 128(N), K chunks of 64 bf16. 256 thr = 8 warps (2m x 4n),
// warp tile 64x32. 3 passes: Ah*Bh + Ah*Bl + Al*Bh. 2-stage cp.async pipeline.
#define MT_TILE  16384                       // 128 rows x 128 B (64 bf16)
#define MT_STAGE (4 * MT_TILE)               // Ah, Al, Bh, Bl
#define MT_SMEM  (2 * MT_STAGE)              // 131072 B

__device__ __forceinline__ void mt_prefetch(
    uint32_t st, const __nv_bfloat16* Ah, const __nv_bfloat16* Al,
    const __nv_bfloat16* Bh, const __nv_bfloat16* Bl,
    int m0, int n0, int k0, int K, int tid)
{
#pragma unroll
    for (int i = 0; i < 4; ++i) {
        int idx = tid + i * 256;             // 0..1023
        int r   = idx >> 3;                  // 0..127
        int s   = idx & 7;                   // 16B segment
        uint32_t sw = swz(r * 128 + s * 16);
        size_t ga = (size_t)(m0 + r) * K + k0 + s * 8;
        size_t gb = (size_t)(n0 + r) * K + k0 + s * 8;
        cp16(st + sw,               Ah + ga);
        cp16(st + MT_TILE + sw,     Al + ga);
        cp16(st + 2 * MT_TILE + sw, Bh + gb);
        cp16(st + 3 * MT_TILE + sw, Bl + gb);
    }
    cp_commit();
}

__global__ __launch_bounds__(256) void gemm_mma_kernel(
    const __nv_bfloat16* __restrict__ Ah, const __nv_bfloat16* __restrict__ Al,
    const __nv_bfloat16* __restrict__ Bh, const __nv_bfloat16* __restrict__ Bl,
    float* __restrict__ C, int M, int N, int K)
{
    extern __shared__ __align__(1024) char smc[];
    const uint32_t sbase = smem_u32(smc);
    const int tid  = threadIdx.x;
    const int wid  = tid >> 5;
    const int lane = tid & 31;
    const int wm   = wid & 1;                // 2 m-groups of 64
    const int wn   = wid >> 1;               // 4 n-groups of 32
    const int m0 = blockIdx.y * 128;
    const int n0 = blockIdx.x * 128;

    float acc[4][4][4];
#pragma unroll
    for (int i = 0; i < 4; i++)
#pragma unroll
        for (int j = 0; j < 4; j++)
#pragma unroll
            for (int r = 0; r < 4; r++) acc[i][j][r] = 0.f;

    const int nch = K >> 6;                  // 64-wide chunks
    mt_prefetch(sbase, Ah, Al, Bh, Bl, m0, n0, 0, K, tid);

    for (int c = 0; c < nch; ++c) {
        if (c + 1 < nch) {
            mt_prefetch(sbase + ((c + 1) & 1) * MT_STAGE,
                        Ah, Al, Bh, Bl, m0, n0, (c + 1) << 6, K, tid);
            cp_wait<1>();
        } else {
            cp_wait<0>();
        }
        __syncthreads();

        const uint32_t sA = sbase + (c & 1) * MT_STAGE;
        const uint32_t sB = sA + 2 * MT_TILE;

        // per-lane ldmatrix row/segment bases
        const int a_row = wm * 64 + (lane & 15);
        const int a_sg  = lane >> 4;                       // k-half
        const int b_row = wn * 32 + ((lane >> 4) << 3) + (lane & 7);
        const int b_sg  = (lane >> 3) & 1;

#pragma unroll
        for (int ks = 0; ks < 4; ++ks) {
            uint32_t ah[4][4], al[4][4], bh[2][4], bl[2][4];
#pragma unroll
            for (int i = 0; i < 4; ++i) {
                uint32_t off = swz((a_row + i * 16) * 128 + (2 * ks + a_sg) * 16);
                LDSM_X4(ah[i], sA + off);
                LDSM_X4(al[i], sA + MT_TILE + off);
            }
#pragma unroll
            for (int jp = 0; jp < 2; ++jp) {
                uint32_t off = swz((b_row + jp * 16) * 128 + (2 * ks + b_sg) * 16);
                LDSM_X4(bh[jp], sB + off);
                LDSM_X4(bl[jp], sB + MT_TILE + off);
            }
#pragma unroll
            for (int i = 0; i < 4; ++i)
#pragma unroll
                for (int j = 0; j < 4; ++j) {
                    uint32_t b0h = bh[j >> 1][(j & 1) * 2];
                    uint32_t b1h = bh[j >> 1][(j & 1) * 2 + 1];
                    uint32_t b0l = bl[j >> 1][(j & 1) * 2];
                    uint32_t b1l = bl[j >> 1][(j & 1) * 2 + 1];
                    mma_bf16(acc[i][j], ah[i], b0h, b1h);
                    mma_bf16(acc[i][j], ah[i], b0l, b1l);
                    mma_bf16(acc[i][j], al[i], b0h, b1h);
                }
        }
        __syncthreads();     // stage (c&1) free for prefetch of chunk c+2
    }

    // epilogue: standard m16n8 C fragment layout
#pragma unroll
    for (int i = 0; i < 4; ++i) {
        int row = m0 + wm * 64 + i * 16 + (lane >> 2);
#pragma unroll
        for (int j = 0; j < 4; ++j) {
            int col = n0 + wn * 32 + j * 8 + (lane & 3) * 2;
            *(float2*)(C + (size_t)row * N + col) =
                make_float2(acc[i][j][0], acc[i][j][1]);
            *(float2*)(C + (size_t)(row + 8) * N + col) =
                make_float2(acc[i][j][2], acc[i][j][3]);
        }
    }
}

// ---------------- RoPE (LongLlama convention: emb = cat(freqs, freqs)) ------
__global__ void rope_kernel(float* __restrict__ Q, float* __restrict__ K,
                            const int* __restrict__ pos)
{
    int s = blockIdx.x;
    int t = threadIdx.x;          // 1024 threads: (h, d<64)
    int h = t >> 6;
    int d = t & 63;

    float tp = (float)(pos[s] - g_minpos);
    float invf = (float)exp(-log(10000.0) * ((double)(2 * d) / 128.0));
    float ang = tp * invf;
    float c, sn;
    sincosf(ang, &sn, &c);

    size_t base = (size_t)s * HID + h * DHEAD;
    float q1 = Q[base + d], q2 = Q[base + d + 64];
    Q[base + d]      = q1 * c - q2 * sn;
    Q[base + d + 64] = q2 * c + q1 * sn;
    float k1 = K[base + d], k2 = K[base + d + 64];
    K[base + d]      = k1 * c - k2 * sn;
    K[base + d + 64] = k2 * c + k1 * sn;
}

// ---------------- flash attention, fp32, causal-block-skipping --------------
#define QK_STRIDE 132
#define SS_STRIDE 68
#define ATT_SMEM_FLOATS (64 * QK_STRIDE * 2 + 64 * 128 + 64 * SS_STRIDE)

__global__ __launch_bounds__(256) void attn_kernel(
    const float* __restrict__ Q, const float* __restrict__ K,
    const float* __restrict__ V, const float* __restrict__ mask,
    float* __restrict__ O)
{
    extern __shared__ float smf[];
    float* Qs = smf;                      // [64][132]
    float* Ks = Qs + 64 * QK_STRIDE;      // [64][132]
    float* Vs = Ks + 64 * QK_STRIDE;      // [64][128]
    float* Ss = Vs + 64 * 128;            // [64][68]

    const int t  = threadIdx.x;
    const int qb = blockIdx.x;
    const int h  = blockIdx.y;
    const int q0 = qb * 64;
    const int tq = t >> 4;                // 0..15
    const int tk = t & 15;                // 0..15

    for (int i = t; i < 64 * 32; i += 256) {
        int r = i >> 5, c = (i & 31) << 2;
        *(float4*)(Qs + r * QK_STRIDE + c) =
            *(const float4*)(Q + (size_t)(q0 + r) * HID + h * DHEAD + c);
    }

    float m_run[4], l_run[4], o[4][8];
#pragma unroll
    for (int i = 0; i < 4; i++) {
        m_run[i] = -INFINITY; l_run[i] = 0.f;
#pragma unroll
        for (int j = 0; j < 8; j++) o[i][j] = 0.f;
    }

    const float scale = 0.08838834764831845f;   // 1/sqrt(128)

    for (int b = 0; b <= qb; b++) {
        const int k0 = b * 64;
        __syncthreads();
        for (int i = t; i < 64 * 32; i += 256) {
            int r = i >> 5, c = (i & 31) << 2;
            *(float4*)(Ks + r * QK_STRIDE + c) =
                *(const float4*)(K + (size_t)(k0 + r) * HID + h * DHEAD + c);
            *(float4*)(Vs + r * 128 + c) =
                *(const float4*)(V + (size_t)(k0 + r) * HID + h * DHEAD + c);
        }
        __syncthreads();

        float acc[4][4];
#pragma unroll
        for (int i = 0; i < 4; i++)
#pragma unroll
            for (int j = 0; j < 4; j++) acc[i][j] = 0.f;

#pragma unroll 8
        for (int d = 0; d < 128; d += 4) {
            float4 qv[4], kv[4];
#pragma unroll
            for (int i = 0; i < 4; i++)
                qv[i] = *(const float4*)(Qs + (tq + 16 * i) * QK_STRIDE + d);
#pragma unroll
            for (int j = 0; j < 4; j++)
                kv[j] = *(const float4*)(Ks + (tk + 16 * j) * QK_STRIDE + d);
#pragma unroll
            for (int i = 0; i < 4; i++)
#pragma unroll
                for (int j = 0; j < 4; j++)
                    acc[i][j] += qv[i].x * kv[j].x + qv[i].y * kv[j].y +
                                 qv[i].z * kv[j].z + qv[i].w * kv[j].w;
        }

#pragma unroll
        for (int i = 0; i < 4; i++) {
            int q = q0 + tq + 16 * i;
            const float* mrow = mask + (size_t)q * S_LEN + k0;
            float rmax = -INFINITY;
#pragma unroll
            for (int j = 0; j < 4; j++) {
                acc[i][j] = acc[i][j] * scale + mrow[tk + 16 * j];
                rmax = fmaxf(rmax, acc[i][j]);
            }
            rmax = fmaxf(rmax, __shfl_xor_sync(0xffffffffu, rmax, 8));
            rmax = fmaxf(rmax, __shfl_xor_sync(0xffffffffu, rmax, 4));
            rmax = fmaxf(rmax, __shfl_xor_sync(0xffffffffu, rmax, 2));
            rmax = fmaxf(rmax, __shfl_xor_sync(0xffffffffu, rmax, 1));
            float mnew = fmaxf(m_run[i], rmax);
            float fac  = expf(m_run[i] - mnew);
            float rsum = 0.f;
#pragma unroll
            for (int j = 0; j < 4; j++) {
                float p = expf(acc[i][j] - mnew);
                Ss[(tq + 16 * i) * SS_STRIDE + tk + 16 * j] = p;
                rsum += p;
            }
            rsum += __shfl_xor_sync(0xffffffffu, rsum, 8);
            rsum += __shfl_xor_sync(0xffffffffu, rsum, 4);
            rsum += __shfl_xor_sync(0xffffffffu, rsum, 2);
            rsum += __shfl_xor_sync(0xffffffffu, rsum, 1);
            l_run[i] = l_run[i] * fac + rsum;
            m_run[i] = mnew;
#pragma unroll
            for (int j = 0; j < 8; j++) o[i][j] *= fac;
        }
        __syncthreads();

#pragma unroll 4
        for (int k = 0; k < 64; k++) {
            float4 v0 = *(const float4*)(Vs + k * 128 + tk * 8);
            float4 v1 = *(const float4*)(Vs + k * 128 + tk * 8 + 4);
#pragma unroll
            for (int i = 0; i < 4; i++) {
                float p = Ss[(tq + 16 * i) * SS_STRIDE + k];
                o[i][0] = fmaf(p, v0.x, o[i][0]);
                o[i][1] = fmaf(p, v0.y, o[i][1]);
                o[i][2] = fmaf(p, v0.z, o[i][2]);
                o[i][3] = fmaf(p, v0.w, o[i][3]);
                o[i][4] = fmaf(p, v1.x, o[i][4]);
                o[i][5] = fmaf(p, v1.y, o[i][5]);
                o[i][6] = fmaf(p, v1.z, o[i][6]);
                o[i][7] = fmaf(p, v1.w, o[i][7]);
            }
        }
    }

#pragma unroll
    for (int i = 0; i < 4; i++) {
        int q = q0 + tq + 16 * i;
        float inv = 1.f / l_run[i];
        float* op = O + (size_t)q * HID + h * DHEAD + tk * 8;
        *(float4*)op = make_float4(o[i][0] * inv, o[i][1] * inv,
                                   o[i][2] * inv, o[i][3] * inv);
        *(float4*)(op + 4) = make_float4(o[i][4] * inv, o[i][5] * inv,
                                         o[i][6] * inv, o[i][7] * inv);
    }
}

// ---------------- launch ----------------------------------------------------
extern "C" void kernel_launch(void* const* d_in, const int* in_sizes, int n_in,
                              void* d_out, int out_size)
{
    const float* X    = (const float*)d_in[0];
    const float* mask = (const float*)d_in[1];
    const int*   pos  = (const int*)d_in[2];   // JAX x64 disabled: int32
    const float* Wq   = (const float*)d_in[3];
    const float* Wk   = (const float*)d_in[4];
    const float* Wv   = (const float*)d_in[5];
    const float* Wo   = (const float*)d_in[6];
    float*       out  = (float*)d_out;

    float *Qp, *Kp, *Vp, *Op;
    __nv_bfloat16 *Xh, *Xl, *Wh, *Wl, *Aoh, *Aol;
    cudaGetSymbolAddress((void**)&Qp, g_Q);
    cudaGetSymbolAddress((void**)&Kp, g_K);
    cudaGetSymbolAddress((void**)&Vp, g_V);
    cudaGetSymbolAddress((void**)&Op, g_Ao);
    cudaGetSymbolAddress((void**)&Xh, g_Xh);
    cudaGetSymbolAddress((void**)&Xl, g_Xl);
    cudaGetSymbolAddress((void**)&Wh, g_Wh);
    cudaGetSymbolAddress((void**)&Wl, g_Wl);
    cudaGetSymbolAddress((void**)&Aoh, g_Aoh);
    cudaGetSymbolAddress((void**)&Aol, g_Aol);

    minpos_kernel<<<1, 256>>>(pos, S_LEN);

    const int xn4 = (S_LEN * HID) / 4;
    const int wn4 = (HID * HID) / 4;
    split_kernel<<<xn4 / 256, 256>>>(X, Xh, Xl, xn4);
    split_kernel<<<wn4 / 256, 256>>>(Wq, Wh + 0 * W_SZ, Wl + 0 * W_SZ, wn4);
    split_kernel<<<wn4 / 256, 256>>>(Wk, Wh + 1 * W_SZ, Wl + 1 * W_SZ, wn4);
    split_kernel<<<wn4 / 256, 256>>>(Wv, Wh + 2 * W_SZ, Wl + 2 * W_SZ, wn4);
    split_kernel<<<wn4 / 256, 256>>>(Wo, Wh + 3 * W_SZ, Wl + 3 * W_SZ, wn4);

    cudaFuncSetAttribute(gemm_mma_kernel,
                         cudaFuncAttributeMaxDynamicSharedMemorySize, MT_SMEM);
    dim3 gg(HID / 128, S_LEN / 128);           // (16, 32)
    gemm_mma_kernel<<<gg, 256, MT_SMEM>>>(Xh, Xl, Wh + 0 * W_SZ, Wl + 0 * W_SZ,
                                          Qp, S_LEN, HID, HID);
    gemm_mma_kernel<<<gg, 256, MT_SMEM>>>(Xh, Xl, Wh + 1 * W_SZ, Wl + 1 * W_SZ,
                                          Kp, S_LEN, HID, HID);
    gemm_mma_kernel<<<gg, 256, MT_SMEM>>>(Xh, Xl, Wh + 2 * W_SZ, Wl + 2 * W_SZ,
                                          Vp, S_LEN, HID, HID);

    rope_kernel<<<S_LEN, 1024>>>(Qp, Kp, pos);

    int smem_bytes = ATT_SMEM_FLOATS * (int)sizeof(float);   // ~117.8 KB
    cudaFuncSetAttribute(attn_kernel,
                         cudaFuncAttributeMaxDynamicSharedMemorySize, smem_bytes);
    dim3 ag(S_LEN / 64, NHEAD);                // (64, 16)
    attn_kernel<<<ag, 256, smem_bytes>>>(Qp, Kp, Vp, mask, Op);

    split_kernel<<<xn4 / 256, 256>>>(Op, Aoh, Aol, xn4);
    gemm_mma_kernel<<<gg, 256, MT_SMEM>>>(Aoh, Aol, Wh + 3 * W_SZ, Wl + 3 * W_SZ,
                                          out, S_LEN, HID, HID);
}

// round 12
// speedup vs baseline: 3.1629x; 1.9400x over previous
#include <cuda_runtime.h>
#include <cuda_bf16.h>
#include <math.h>
#include <stdint.h>

#define S_LEN 4096
#define HID   2048
#define NHEAD 16
#define DHEAD 128
#define W_SZ  ((size_t)HID * HID)

// ---------------- scratch (device globals; no allocations allowed) ----------
__device__ float g_Q[(size_t)S_LEN * HID];
__device__ float g_K[(size_t)S_LEN * HID];
__device__ float g_V[(size_t)S_LEN * HID];
__device__ float g_Ao[(size_t)S_LEN * HID];
__device__ __align__(16) __nv_bfloat16 g_Xh[(size_t)S_LEN * HID];
__device__ __align__(16) __nv_bfloat16 g_Xl[(size_t)S_LEN * HID];
__device__ __align__(16) __nv_bfloat16 g_Wh[4 * W_SZ];
__device__ __align__(16) __nv_bfloat16 g_Wl[4 * W_SZ];
__device__ __align__(16) __nv_bfloat16 g_Aoh[(size_t)S_LEN * HID];
__device__ __align__(16) __nv_bfloat16 g_Aol[(size_t)S_LEN * HID];
// bf16 hi/lo of rope'd Q, K and of V for tensor-core attention
__device__ __align__(16) __nv_bfloat16 g_Qbh[(size_t)S_LEN * HID];
__device__ __align__(16) __nv_bfloat16 g_Qbl[(size_t)S_LEN * HID];
__device__ __align__(16) __nv_bfloat16 g_Kbh[(size_t)S_LEN * HID];
__device__ __align__(16) __nv_bfloat16 g_Kbl[(size_t)S_LEN * HID];
__device__ __align__(16) __nv_bfloat16 g_Vbh[(size_t)S_LEN * HID];
__device__ __align__(16) __nv_bfloat16 g_Vbl[(size_t)S_LEN * HID];
__device__ int g_minpos;

// ---------------- PTX helpers (all sm_80-era: valid on compute_103) ---------
__device__ __forceinline__ uint32_t smem_u32(const void* p) {
    uint32_t a;
    asm("{ .reg .u64 t; cvta.to.shared.u64 t, %1; cvt.u32.u64 %0, t; }"
        : "=r"(a) : "l"(p));
    return a;
}

__device__ __forceinline__ void cp16(uint32_t saddr, const void* g) {
    asm volatile("cp.async.cg.shared.global [%0], [%1], 16;"
                 :: "r"(saddr), "l"(g) : "memory");
}
__device__ __forceinline__ void cp_commit() {
    asm volatile("cp.async.commit_group;" ::: "memory");
}
template <int N>
__device__ __forceinline__ void cp_wait() {
    asm volatile("cp.async.wait_group %0;" :: "n"(N) : "memory");
}

#define LDSM_X4(r, addr) \
    asm volatile("ldmatrix.sync.aligned.m8n8.x4.shared.b16 {%0,%1,%2,%3}, [%4];" \
                 : "=r"((r)[0]), "=r"((r)[1]), "=r"((r)[2]), "=r"((r)[3]) \
                 : "r"(addr))

#define LDSM_X4T(r, addr) \
    asm volatile("ldmatrix.sync.aligned.m8n8.x4.trans.shared.b16 {%0,%1,%2,%3}, [%4];" \
                 : "=r"((r)[0]), "=r"((r)[1]), "=r"((r)[2]), "=r"((r)[3]) \
                 : "r"(addr))

__device__ __forceinline__ void mma_bf16(float* c, const uint32_t* a,
                                         uint32_t b0, uint32_t b1) {
    asm volatile(
        "mma.sync.aligned.m16n8k16.row.col.f32.bf16.bf16.f32 "
        "{%0,%1,%2,%3}, {%4,%5,%6,%7}, {%8,%9}, {%0,%1,%2,%3};"
        : "+f"(c[0]), "+f"(c[1]), "+f"(c[2]), "+f"(c[3])
        : "r"(a[0]), "r"(a[1]), "r"(a[2]), "r"(a[3]), "r"(b0), "r"(b1));
}

__device__ __forceinline__ uint32_t swz(uint32_t boff) {   // SW128-style
    return boff ^ ((boff >> 3) & 0x70);
}

__device__ __forceinline__ void pack_hl(float x, float y,
                                        uint32_t& h, uint32_t& l) {
    __nv_bfloat162 hh = __floats2bfloat162_rn(x, y);
    h = *reinterpret_cast<uint32_t*>(&hh);
    __nv_bfloat162 ll = __floats2bfloat162_rn(x - __low2float(hh),
                                              y - __high2float(hh));
    l = *reinterpret_cast<uint32_t*>(&ll);
}

// ---------------- min(position_ids)  (JAX demotes int64->int32) -------------
__global__ void minpos_kernel(const int* __restrict__ pos, int n)
{
    __shared__ int sm[256];
    int v = 0x7fffffff;
    for (int i = threadIdx.x; i < n; i += 256) {
        int p = pos[i];
        v = (p < v) ? p : v;
    }
    sm[threadIdx.x] = v;
    __syncthreads();
    for (int s = 128; s > 0; s >>= 1) {
        if (threadIdx.x < s) {
            int o = sm[threadIdx.x + s];
            if (o < sm[threadIdx.x]) sm[threadIdx.x] = o;
        }
        __syncthreads();
    }
    if (threadIdx.x == 0) g_minpos = sm[0];
}

// ---------------- fp32 -> (bf16 hi, bf16 lo) split ---------------------------
__global__ void split_kernel(const float* __restrict__ x,
                             __nv_bfloat16* __restrict__ hi,
                             __nv_bfloat16* __restrict__ lo, int n4)
{
    int i = blockIdx.x * blockDim.x + threadIdx.x;
    if (i >= n4) return;
    float4 v = ((const float4*)x)[i];
    float f[4] = {v.x, v.y, v.z, v.w};
    __nv_bfloat16 h[4], l[4];
#pragma unroll
    for (int j = 0; j < 4; ++j) {
        h[j] = __float2bfloat16(f[j]);
        l[j] = __float2bfloat16(f[j] - __bfloat162float(h[j]));
    }
    ((uint2*)hi)[i] = *(uint2*)h;
    ((uint2*)lo)[i] = *(uint2*)l;
}

// ---------------- mma.sync bf16-split GEMM: C = A * B^T ---------------------
#define MT_TILE  16384
#define MT_STAGE (4 * MT_TILE)
#define MT_SMEM  (2 * MT_STAGE)

__device__ __forceinline__ void mt_prefetch(
    uint32_t st, const __nv_bfloat16* Ah, const __nv_bfloat16* Al,
    const __nv_bfloat16* Bh, const __nv_bfloat16* Bl,
    int m0, int n0, int k0, int K, int tid)
{
#pragma unroll
    for (int i = 0; i < 4; ++i) {
        int idx = tid + i * 256;
        int r   = idx >> 3;
        int s   = idx & 7;
        uint32_t sw = swz(r * 128 + s * 16);
        size_t ga = (size_t)(m0 + r) * K + k0 + s * 8;
        size_t gb = (size_t)(n0 + r) * K + k0 + s * 8;
        cp16(st + sw,               Ah + ga);
        cp16(st + MT_TILE + sw,     Al + ga);
        cp16(st + 2 * MT_TILE + sw, Bh + gb);
        cp16(st + 3 * MT_TILE + sw, Bl + gb);
    }
    cp_commit();
}

__global__ __launch_bounds__(256) void gemm_mma_kernel(
    const __nv_bfloat16* __restrict__ Ah, const __nv_bfloat16* __restrict__ Al,
    const __nv_bfloat16* __restrict__ Bh, const __nv_bfloat16* __restrict__ Bl,
    float* __restrict__ C, int M, int N, int K)
{
    extern __shared__ __align__(1024) char smc[];
    const uint32_t sbase = smem_u32(smc);
    const int tid  = threadIdx.x;
    const int wid  = tid >> 5;
    const int lane = tid & 31;
    const int wm   = wid & 1;
    const int wn   = wid >> 1;
    const int m0 = blockIdx.y * 128;
    const int n0 = blockIdx.x * 128;

    float acc[4][4][4];
#pragma unroll
    for (int i = 0; i < 4; i++)
#pragma unroll
        for (int j = 0; j < 4; j++)
#pragma unroll
            for (int r = 0; r < 4; r++) acc[i][j][r] = 0.f;

    const int nch = K >> 6;
    mt_prefetch(sbase, Ah, Al, Bh, Bl, m0, n0, 0, K, tid);

    for (int c = 0; c < nch; ++c) {
        if (c + 1 < nch) {
            mt_prefetch(sbase + ((c + 1) & 1) * MT_STAGE,
                        Ah, Al, Bh, Bl, m0, n0, (c + 1) << 6, K, tid);
            cp_wait<1>();
        } else {
            cp_wait<0>();
        }
        __syncthreads();

        const uint32_t sA = sbase + (c & 1) * MT_STAGE;
        const uint32_t sB = sA + 2 * MT_TILE;

        const int a_row = wm * 64 + (lane & 15);
        const int a_sg  = lane >> 4;
        const int b_row = wn * 32 + ((lane >> 4) << 3) + (lane & 7);
        const int b_sg  = (lane >> 3) & 1;

#pragma unroll
        for (int ks = 0; ks < 4; ++ks) {
            uint32_t ah[4][4], al[4][4], bh[2][4], bl[2][4];
#pragma unroll
            for (int i = 0; i < 4; ++i) {
                uint32_t off = swz((a_row + i * 16) * 128 + (2 * ks + a_sg) * 16);
                LDSM_X4(ah[i], sA + off);
                LDSM_X4(al[i], sA + MT_TILE + off);
            }
#pragma unroll
            for (int jp = 0; jp < 2; ++jp) {
                uint32_t off = swz((b_row + jp * 16) * 128 + (2 * ks + b_sg) * 16);
                LDSM_X4(bh[jp], sB + off);
                LDSM_X4(bl[jp], sB + MT_TILE + off);
            }
#pragma unroll
            for (int i = 0; i < 4; ++i)
#pragma unroll
                for (int j = 0; j < 4; ++j) {
                    uint32_t b0h = bh[j >> 1][(j & 1) * 2];
                    uint32_t b1h = bh[j >> 1][(j & 1) * 2 + 1];
                    uint32_t b0l = bl[j >> 1][(j & 1) * 2];
                    uint32_t b1l = bl[j >> 1][(j & 1) * 2 + 1];
                    mma_bf16(acc[i][j], ah[i], b0h, b1h);
                    mma_bf16(acc[i][j], ah[i], b0l, b1l);
                    mma_bf16(acc[i][j], al[i], b0h, b1h);
                }
        }
        __syncthreads();
    }

#pragma unroll
    for (int i = 0; i < 4; ++i) {
        int row = m0 + wm * 64 + i * 16 + (lane >> 2);
#pragma unroll
        for (int j = 0; j < 4; ++j) {
            int col = n0 + wn * 32 + j * 8 + (lane & 3) * 2;
            *(float2*)(C + (size_t)row * N + col) =
                make_float2(acc[i][j][0], acc[i][j][1]);
            *(float2*)(C + (size_t)(row + 8) * N + col) =
                make_float2(acc[i][j][2], acc[i][j][3]);
        }
    }
}

// ---------------- RoPE + bf16 hi/lo split (fused) ----------------------------
__global__ void rope_split_kernel(const float* __restrict__ Q,
                                  const float* __restrict__ K,
                                  const int* __restrict__ pos,
                                  __nv_bfloat16* __restrict__ Qh,
                                  __nv_bfloat16* __restrict__ Ql,
                                  __nv_bfloat16* __restrict__ Kh,
                                  __nv_bfloat16* __restrict__ Kl)
{
    int s = blockIdx.x;
    int t = threadIdx.x;          // 1024 threads: (h, d<64)
    int h = t >> 6;
    int d = t & 63;

    float tp = (float)(pos[s] - g_minpos);
    float invf = (float)exp(-log(10000.0) * ((double)(2 * d) / 128.0));
    float ang = tp * invf;
    float c, sn;
    sincosf(ang, &sn, &c);

    size_t base = (size_t)s * HID + h * DHEAD;
    float q1 = Q[base + d], q2 = Q[base + d + 64];
    float k1 = K[base + d], k2 = K[base + d + 64];
    float qa = q1 * c - q2 * sn, qb = q2 * c + q1 * sn;
    float ka = k1 * c - k2 * sn, kb = k2 * c + k1 * sn;

    __nv_bfloat16 hq;
    hq = __float2bfloat16(qa); Qh[base + d] = hq;
    Ql[base + d]      = __float2bfloat16(qa - __bfloat162float(hq));
    hq = __float2bfloat16(qb); Qh[base + d + 64] = hq;
    Ql[base + d + 64] = __float2bfloat16(qb - __bfloat162float(hq));
    hq = __float2bfloat16(ka); Kh[base + d] = hq;
    Kl[base + d]      = __float2bfloat16(ka - __bfloat162float(hq));
    hq = __float2bfloat16(kb); Kh[base + d + 64] = hq;
    Kl[base + d + 64] = __float2bfloat16(kb - __bfloat162float(hq));
}

// ---------------- tensor-core flash attention --------------------------------
// CTA = 128 q-rows x 1 head. 8 warps x 16 rows. k-blocks of 64, double-buffered.
// QK^T and P.V: 3-pass bf16 hi/lo. Causal mask synthesized (= reference values).
// smem: Q hi/lo 64K @0 | K stages 2x32K @64K | V stages 2x32K @128K = 192K.
#define AT_SQ  0
#define AT_SK  65536
#define AT_SV  131072
#define AT_SMEM 196608

__device__ __forceinline__ void at_prefetch_kv(
    uint32_t sb, int stage, const __nv_bfloat16* Kh, const __nv_bfloat16* Kl,
    const __nv_bfloat16* Vh, const __nv_bfloat16* Vl,
    int k0, int h, int tid)
{
    const uint32_t sK = sb + AT_SK + stage * 32768;
    const uint32_t sV = sb + AT_SV + stage * 32768;
#pragma unroll
    for (int i = 0; i < 8; ++i) {             // K: 2048 cp16
        int idx = tid + i * 256;
        int hl = idx >> 10, rem = idx & 1023;
        int r = rem >> 4, dc = rem & 15;
        uint32_t sa = sK + hl * 16384 + (dc >> 3) * 8192
                    + swz(r * 128 + (dc & 7) * 16);
        const __nv_bfloat16* g = hl ? Kl : Kh;
        cp16(sa, g + (size_t)(k0 + r) * HID + h * DHEAD + dc * 8);
    }
#pragma unroll
    for (int i = 0; i < 8; ++i) {             // V: 2048 cp16
        int idx = tid + i * 256;
        int hl = idx >> 10, rem = idx & 1023;
        int r = rem >> 4, dc = rem & 15;
        uint32_t sa = sV + hl * 16384 + (dc >> 3) * 8192
                    + swz(r * 128 + (dc & 7) * 16);
        const __nv_bfloat16* g = hl ? Vl : Vh;
        cp16(sa, g + (size_t)(k0 + r) * HID + h * DHEAD + dc * 8);
    }
    cp_commit();
}

__global__ __launch_bounds__(256) void attn_mma_kernel(
    const __nv_bfloat16* __restrict__ Qh, const __nv_bfloat16* __restrict__ Ql,
    const __nv_bfloat16* __restrict__ Kh, const __nv_bfloat16* __restrict__ Kl,
    const __nv_bfloat16* __restrict__ Vh, const __nv_bfloat16* __restrict__ Vl,
    float* __restrict__ O)
{
    extern __shared__ __align__(1024) char smb[];
    const uint32_t sb = smem_u32(smb);
    const int tid  = threadIdx.x;
    const int wid  = tid >> 5;
    const int lane = tid & 31;
    const int qb = (int)(gridDim.x - 1 - blockIdx.x);   // big blocks first
    const int h  = blockIdx.y;
    const int q0 = qb * 128;
    const int nkb = 2 * qb + 2;

    // Q tile (hi/lo): layout [hl][kh][128 rows][128B], loaded once
    {
#pragma unroll
        for (int i = 0; i < 16; ++i) {
            int idx = tid + i * 256;          // 0..4095
            int hl = idx >> 11, rem = idx & 2047;
            int r = rem >> 4, dc = rem & 15;
            uint32_t sa = sb + AT_SQ + hl * 32768 + (dc >> 3) * 16384
                        + swz(r * 128 + (dc & 7) * 16);
            const __nv_bfloat16* g = hl ? Ql : Qh;
            cp16(sa, g + (size_t)(q0 + r) * HID + h * DHEAD + dc * 8);
        }
    }
    at_prefetch_kv(sb, 0, Kh, Kl, Vh, Vl, 0, h, tid);  // commits Q+stage0

    const float scale = 0.08838834764831845f;          // 1/sqrt(128)
    float o[16][4];
#pragma unroll
    for (int t = 0; t < 16; ++t)
#pragma unroll
        for (int r = 0; r < 4; ++r) o[t][r] = 0.f;
    float m0r = -INFINITY, m1r = -INFINITY, l0r = 0.f, l1r = 0.f;

    const int qrow0 = q0 + wid * 16 + (lane >> 2);
    const int qrow1 = qrow0 + 8;

    for (int c = 0; c < nkb; ++c) {
        if (c + 1 < nkb) {
            at_prefetch_kv(sb, (c + 1) & 1, Kh, Kl, Vh, Vl, (c + 1) * 64, h, tid);
            cp_wait<1>();
        } else {
            cp_wait<0>();
        }
        __syncthreads();

        const uint32_t sK = sb + AT_SK + (c & 1) * 32768;
        const uint32_t sV = sb + AT_SV + (c & 1) * 32768;
        const int k0 = c * 64;

        // ---- S = Q K^T  (128x64, warp owns 16 rows) ----
        float sacc[8][4];
#pragma unroll
        for (int j = 0; j < 8; ++j)
#pragma unroll
            for (int r = 0; r < 4; ++r) sacc[j][r] = 0.f;

#pragma unroll
        for (int ks = 0; ks < 8; ++ks) {
            const int kh = ks >> 2, sg = ks & 3;
            uint32_t ah[4], al[4];
            uint32_t qoff = kh * 16384 +
                swz((wid * 16 + (lane & 15)) * 128 + (2 * sg + (lane >> 4)) * 16);
            LDSM_X4(ah, sb + AT_SQ + qoff);
            LDSM_X4(al, sb + AT_SQ + 32768 + qoff);
#pragma unroll
            for (int ng = 0; ng < 4; ++ng) {
                uint32_t bh[4], bl[4];
                uint32_t koff = kh * 8192 +
                    swz((ng * 16 + ((lane >> 4) << 3) + (lane & 7)) * 128 +
                        (2 * sg + ((lane >> 3) & 1)) * 16);
                LDSM_X4(bh, sK + koff);
                LDSM_X4(bl, sK + 16384 + koff);
                mma_bf16(sacc[2 * ng],     ah, bh[0], bh[1]);
                mma_bf16(sacc[2 * ng],     ah, bl[0], bl[1]);
                mma_bf16(sacc[2 * ng],     al, bh[0], bh[1]);
                mma_bf16(sacc[2 * ng + 1], ah, bh[2], bh[3]);
                mma_bf16(sacc[2 * ng + 1], ah, bl[2], bl[3]);
                mma_bf16(sacc[2 * ng + 1], al, bh[2], bh[3]);
            }
        }

        // ---- scale + causal mask + online softmax ----
        const bool domask = (k0 + 63) > q0;   // only last two blocks
        float mx0 = -INFINITY, mx1 = -INFINITY;
#pragma unroll
        for (int j = 0; j < 8; ++j) {
            int col = k0 + j * 8 + (lane & 3) * 2;
            if (domask) {
                sacc[j][0] = sacc[j][0] * scale + ((col     > qrow0) ? -1e9f : 0.f);
                sacc[j][1] = sacc[j][1] * scale + ((col + 1 > qrow0) ? -1e9f : 0.f);
                sacc[j][2] = sacc[j][2] * scale + ((col     > qrow1) ? -1e9f : 0.f);
                sacc[j][3] = sacc[j][3] * scale + ((col + 1 > qrow1) ? -1e9f : 0.f);
            } else {
                sacc[j][0] *= scale; sacc[j][1] *= scale;
                sacc[j][2] *= scale; sacc[j][3] *= scale;
            }
            mx0 = fmaxf(mx0, fmaxf(sacc[j][0], sacc[j][1]));
            mx1 = fmaxf(mx1, fmaxf(sacc[j][2], sacc[j][3]));
        }
        mx0 = fmaxf(mx0, __shfl_xor_sync(0xffffffffu, mx0, 1));
        mx0 = fmaxf(mx0, __shfl_xor_sync(0xffffffffu, mx0, 2));
        mx1 = fmaxf(mx1, __shfl_xor_sync(0xffffffffu, mx1, 1));
        mx1 = fmaxf(mx1, __shfl_xor_sync(0xffffffffu, mx1, 2));

        float mn0 = fmaxf(m0r, mx0), mn1 = fmaxf(m1r, mx1);
        float fac0 = expf(m0r - mn0), fac1 = expf(m1r - mn1);
        m0r = mn0; m1r = mn1;

        float ls0 = 0.f, ls1 = 0.f;
#pragma unroll
        for (int j = 0; j < 8; ++j) {
            sacc[j][0] = expf(sacc[j][0] - mn0);
            sacc[j][1] = expf(sacc[j][1] - mn0);
            sacc[j][2] = expf(sacc[j][2] - mn1);
            sacc[j][3] = expf(sacc[j][3] - mn1);
            ls0 += sacc[j][0] + sacc[j][1];
            ls1 += sacc[j][2] + sacc[j][3];
        }
        ls0 += __shfl_xor_sync(0xffffffffu, ls0, 1);
        ls0 += __shfl_xor_sync(0xffffffffu, ls0, 2);
        ls1 += __shfl_xor_sync(0xffffffffu, ls1, 1);
        ls1 += __shfl_xor_sync(0xffffffffu, ls1, 2);
        l0r = l0r * fac0 + ls0;
        l1r = l1r * fac1 + ls1;

#pragma unroll
        for (int t = 0; t < 16; ++t) {
            o[t][0] *= fac0; o[t][1] *= fac0;
            o[t][2] *= fac1; o[t][3] *= fac1;
        }

        // ---- O += P V  (P fragments direct from registers) ----
#pragma unroll
        for (int ks = 0; ks < 4; ++ks) {
            uint32_t ph[4], pl[4];
            pack_hl(sacc[2 * ks][0],     sacc[2 * ks][1],     ph[0], pl[0]);
            pack_hl(sacc[2 * ks][2],     sacc[2 * ks][3],     ph[1], pl[1]);
            pack_hl(sacc[2 * ks + 1][0], sacc[2 * ks + 1][1], ph[2], pl[2]);
            pack_hl(sacc[2 * ks + 1][2], sacc[2 * ks + 1][3], ph[3], pl[3]);
#pragma unroll
            for (int ng = 0; ng < 8; ++ng) {
                uint32_t vh[4], vl[4];
                uint32_t voff = (ng >> 2) * 8192 +
                    swz((ks * 16 + (lane & 15)) * 128 +
                        (ng & 3) * 32 + (lane >> 4) * 16);
                LDSM_X4T(vh, sV + voff);
                LDSM_X4T(vl, sV + 16384 + voff);
                mma_bf16(o[2 * ng],     ph, vh[0], vh[1]);
                mma_bf16(o[2 * ng],     ph, vl[0], vl[1]);
                mma_bf16(o[2 * ng],     pl, vh[0], vh[1]);
                mma_bf16(o[2 * ng + 1], ph, vh[2], vh[3]);
                mma_bf16(o[2 * ng + 1], ph, vl[2], vl[3]);
                mma_bf16(o[2 * ng + 1], pl, vh[2], vh[3]);
            }
        }
        __syncthreads();
    }

    // ---- normalize + write ----
    float inv0 = 1.f / l0r, inv1 = 1.f / l1r;
#pragma unroll
    for (int t = 0; t < 16; ++t) {
        size_t col = h * DHEAD + t * 8 + (lane & 3) * 2;
        *(float2*)(O + (size_t)qrow0 * HID + col) =
            make_float2(o[t][0] * inv0, o[t][1] * inv0);
        *(float2*)(O + (size_t)qrow1 * HID + col) =
            make_float2(o[t][2] * inv1, o[t][3] * inv1);
    }
}

// ---------------- launch ----------------------------------------------------
extern "C" void kernel_launch(void* const* d_in, const int* in_sizes, int n_in,
                              void* d_out, int out_size)
{
    const float* X    = (const float*)d_in[0];
    const int*   pos  = (const int*)d_in[2];   // JAX x64 disabled: int32
    const float* Wq   = (const float*)d_in[3];
    const float* Wk   = (const float*)d_in[4];
    const float* Wv   = (const float*)d_in[5];
    const float* Wo   = (const float*)d_in[6];
    float*       out  = (float*)d_out;

    float *Qp, *Kp, *Vp, *Op;
    __nv_bfloat16 *Xh, *Xl, *Wh, *Wl, *Aoh, *Aol;
    __nv_bfloat16 *Qbh, *Qbl, *Kbh, *Kbl, *Vbh, *Vbl;
    cudaGetSymbolAddress((void**)&Qp, g_Q);
    cudaGetSymbolAddress((void**)&Kp, g_K);
    cudaGetSymbolAddress((void**)&Vp, g_V);
    cudaGetSymbolAddress((void**)&Op, g_Ao);
    cudaGetSymbolAddress((void**)&Xh, g_Xh);
    cudaGetSymbolAddress((void**)&Xl, g_Xl);
    cudaGetSymbolAddress((void**)&Wh, g_Wh);
    cudaGetSymbolAddress((void**)&Wl, g_Wl);
    cudaGetSymbolAddress((void**)&Aoh, g_Aoh);
    cudaGetSymbolAddress((void**)&Aol, g_Aol);
    cudaGetSymbolAddress((void**)&Qbh, g_Qbh);
    cudaGetSymbolAddress((void**)&Qbl, g_Qbl);
    cudaGetSymbolAddress((void**)&Kbh, g_Kbh);
    cudaGetSymbolAddress((void**)&Kbl, g_Kbl);
    cudaGetSymbolAddress((void**)&Vbh, g_Vbh);
    cudaGetSymbolAddress((void**)&Vbl, g_Vbl);

    minpos_kernel<<<1, 256>>>(pos, S_LEN);

    const int xn4 = (S_LEN * HID) / 4;
    const int wn4 = (HID * HID) / 4;
    split_kernel<<<xn4 / 256, 256>>>(X, Xh, Xl, xn4);
    split_kernel<<<wn4 / 256, 256>>>(Wq, Wh + 0 * W_SZ, Wl + 0 * W_SZ, wn4);
    split_kernel<<<wn4 / 256, 256>>>(Wk, Wh + 1 * W_SZ, Wl + 1 * W_SZ, wn4);
    split_kernel<<<wn4 / 256, 256>>>(Wv, Wh + 2 * W_SZ, Wl + 2 * W_SZ, wn4);
    split_kernel<<<wn4 / 256, 256>>>(Wo, Wh + 3 * W_SZ, Wl + 3 * W_SZ, wn4);

    cudaFuncSetAttribute(gemm_mma_kernel,
                         cudaFuncAttributeMaxDynamicSharedMemorySize, MT_SMEM);
    dim3 gg(HID / 128, S_LEN / 128);           // (16, 32)
    gemm_mma_kernel<<<gg, 256, MT_SMEM>>>(Xh, Xl, Wh + 0 * W_SZ, Wl + 0 * W_SZ,
                                          Qp, S_LEN, HID, HID);
    gemm_mma_kernel<<<gg, 256, MT_SMEM>>>(Xh, Xl, Wh + 1 * W_SZ, Wl + 1 * W_SZ,
                                          Kp, S_LEN, HID, HID);
    gemm_mma_kernel<<<gg, 256, MT_SMEM>>>(Xh, Xl, Wh + 2 * W_SZ, Wl + 2 * W_SZ,
                                          Vp, S_LEN, HID, HID);

    rope_split_kernel<<<S_LEN, 1024>>>(Qp, Kp, pos, Qbh, Qbl, Kbh, Kbl);
    split_kernel<<<xn4 / 256, 256>>>(Vp, Vbh, Vbl, xn4);

    cudaFuncSetAttribute(attn_mma_kernel,
                         cudaFuncAttributeMaxDynamicSharedMemorySize, AT_SMEM);
    dim3 ag(S_LEN / 128, NHEAD);               // (32, 16)
    attn_mma_kernel<<<ag, 256, AT_SMEM>>>(Qbh, Qbl, Kbh, Kbl, Vbh, Vbl, Op);

    split_kernel<<<xn4 / 256, 256>>>(Op, Aoh, Aol, xn4);
    gemm_mma_kernel<<<gg, 256, MT_SMEM>>>(Aoh, Aol, Wh + 3 * W_SZ, Wl + 3 * W_SZ,
                                          out, S_LEN, HID, HID);
}

// round 13
// speedup vs baseline: 3.3877x; 1.0711x over previous
#include <cuda_runtime.h>
#include <cuda_bf16.h>
#include <math.h>
#include <stdint.h>

#define S_LEN 4096
#define HID   2048
#define NHEAD 16
#define DHEAD 128
#define W_SZ  ((size_t)HID * HID)

// ---------------- scratch (device globals; no allocations allowed) ----------
__device__ float g_Q[(size_t)S_LEN * HID];
__device__ float g_K[(size_t)S_LEN * HID];
__device__ __align__(16) __nv_bfloat16 g_Xh[(size_t)S_LEN * HID];
__device__ __align__(16) __nv_bfloat16 g_Xl[(size_t)S_LEN * HID];
__device__ __align__(16) __nv_bfloat16 g_Wh[4 * W_SZ];
__device__ __align__(16) __nv_bfloat16 g_Wl[4 * W_SZ];
__device__ __align__(16) __nv_bfloat16 g_Aoh[(size_t)S_LEN * HID];
__device__ __align__(16) __nv_bfloat16 g_Aol[(size_t)S_LEN * HID];
__device__ __align__(16) __nv_bfloat16 g_Qbh[(size_t)S_LEN * HID];
__device__ __align__(16) __nv_bfloat16 g_Qbl[(size_t)S_LEN * HID];
__device__ __align__(16) __nv_bfloat16 g_Kbh[(size_t)S_LEN * HID];
__device__ __align__(16) __nv_bfloat16 g_Kbl[(size_t)S_LEN * HID];
__device__ __align__(16) __nv_bfloat16 g_Vbh[(size_t)S_LEN * HID];
__device__ __align__(16) __nv_bfloat16 g_Vbl[(size_t)S_LEN * HID];
__device__ int g_minpos;

// ---------------- PTX helpers (all sm_80-era: valid on compute_103) ---------
__device__ __forceinline__ uint32_t smem_u32(const void* p) {
    uint32_t a;
    asm("{ .reg .u64 t; cvta.to.shared.u64 t, %1; cvt.u32.u64 %0, t; }"
        : "=r"(a) : "l"(p));
    return a;
}

__device__ __forceinline__ void cp16(uint32_t saddr, const void* g) {
    asm volatile("cp.async.cg.shared.global [%0], [%1], 16;"
                 :: "r"(saddr), "l"(g) : "memory");
}
__device__ __forceinline__ void cp_commit() {
    asm volatile("cp.async.commit_group;" ::: "memory");
}
template <int N>
__device__ __forceinline__ void cp_wait() {
    asm volatile("cp.async.wait_group %0;" :: "n"(N) : "memory");
}

#define LDSM_X4(r, addr) \
    asm volatile("ldmatrix.sync.aligned.m8n8.x4.shared.b16 {%0,%1,%2,%3}, [%4];" \
                 : "=r"((r)[0]), "=r"((r)[1]), "=r"((r)[2]), "=r"((r)[3]) \
                 : "r"(addr))

#define LDSM_X4T(r, addr) \
    asm volatile("ldmatrix.sync.aligned.m8n8.x4.trans.shared.b16 {%0,%1,%2,%3}, [%4];" \
                 : "=r"((r)[0]), "=r"((r)[1]), "=r"((r)[2]), "=r"((r)[3]) \
                 : "r"(addr))

__device__ __forceinline__ void mma_bf16(float* c, const uint32_t* a,
                                         uint32_t b0, uint32_t b1) {
    asm volatile(
        "mma.sync.aligned.m16n8k16.row.col.f32.bf16.bf16.f32 "
        "{%0,%1,%2,%3}, {%4,%5,%6,%7}, {%8,%9}, {%0,%1,%2,%3};"
        : "+f"(c[0]), "+f"(c[1]), "+f"(c[2]), "+f"(c[3])
        : "r"(a[0]), "r"(a[1]), "r"(a[2]), "r"(a[3]), "r"(b0), "r"(b1));
}

__device__ __forceinline__ uint32_t swz(uint32_t boff) {   // SW128-style
    return boff ^ ((boff >> 3) & 0x70);
}

__device__ __forceinline__ void pack_hl(float x, float y,
                                        uint32_t& h, uint32_t& l) {
    __nv_bfloat162 hh = __floats2bfloat162_rn(x, y);
    h = *reinterpret_cast<uint32_t*>(&hh);
    __nv_bfloat162 ll = __floats2bfloat162_rn(x - __low2float(hh),
                                              y - __high2float(hh));
    l = *reinterpret_cast<uint32_t*>(&ll);
}

__device__ __forceinline__ float ex2(float x) {
    float y;
    asm("ex2.approx.ftz.f32 %0, %1;" : "=f"(y) : "f"(x));
    return y;
}

// ---------------- min(position_ids)  (JAX demotes int64->int32) -------------
__global__ void minpos_kernel(const int* __restrict__ pos, int n)
{
    __shared__ int sm[256];
    int v = 0x7fffffff;
    for (int i = threadIdx.x; i < n; i += 256) {
        int p = pos[i];
        v = (p < v) ? p : v;
    }
    sm[threadIdx.x] = v;
    __syncthreads();
    for (int s = 128; s > 0; s >>= 1) {
        if (threadIdx.x < s) {
            int o = sm[threadIdx.x + s];
            if (o < sm[threadIdx.x]) sm[threadIdx.x] = o;
        }
        __syncthreads();
    }
    if (threadIdx.x == 0) g_minpos = sm[0];
}

// ---------------- fp32 -> (bf16 hi, bf16 lo) split ---------------------------
__global__ void split_kernel(const float* __restrict__ x,
                             __nv_bfloat16* __restrict__ hi,
                             __nv_bfloat16* __restrict__ lo, int n4)
{
    int i = blockIdx.x * blockDim.x + threadIdx.x;
    if (i >= n4) return;
    float4 v = ((const float4*)x)[i];
    float f[4] = {v.x, v.y, v.z, v.w};
    __nv_bfloat16 h[4], l[4];
#pragma unroll
    for (int j = 0; j < 4; ++j) {
        h[j] = __float2bfloat16(f[j]);
        l[j] = __float2bfloat16(f[j] - __bfloat162float(h[j]));
    }
    ((uint2*)hi)[i] = *(uint2*)h;
    ((uint2*)lo)[i] = *(uint2*)l;
}

// ---------------- mma.sync bf16-split GEMM core ------------------------------
#define MT_TILE  16384
#define MT_STAGE (4 * MT_TILE)
#define MT_SMEM  (2 * MT_STAGE)

__device__ __forceinline__ void mt_prefetch(
    uint32_t st, const __nv_bfloat16* Ah, const __nv_bfloat16* Al,
    const __nv_bfloat16* Bh, const __nv_bfloat16* Bl,
    int m0, int n0, int k0, int K, int tid)
{
#pragma unroll
    for (int i = 0; i < 4; ++i) {
        int idx = tid + i * 256;
        int r   = idx >> 3;
        int s   = idx & 7;
        uint32_t sw = swz(r * 128 + s * 16);
        size_t ga = (size_t)(m0 + r) * K + k0 + s * 8;
        size_t gb = (size_t)(n0 + r) * K + k0 + s * 8;
        cp16(st + sw,               Ah + ga);
        cp16(st + MT_TILE + sw,     Al + ga);
        cp16(st + 2 * MT_TILE + sw, Bh + gb);
        cp16(st + 3 * MT_TILE + sw, Bl + gb);
    }
    cp_commit();
}

// mainloop shared by both GEMM kernels: leaves acc[4][4][4] filled
__device__ __forceinline__ void mt_mainloop(
    float acc[4][4][4], uint32_t sbase,
    const __nv_bfloat16* Ah, const __nv_bfloat16* Al,
    const __nv_bfloat16* Bh, const __nv_bfloat16* Bl,
    int m0, int n0, int K, int tid)
{
    const int wid  = tid >> 5;
    const int lane = tid & 31;
    const int wm   = wid & 1;
    const int wn   = wid >> 1;

    const int nch = K >> 6;
    mt_prefetch(sbase, Ah, Al, Bh, Bl, m0, n0, 0, K, tid);

    for (int c = 0; c < nch; ++c) {
        if (c + 1 < nch) {
            mt_prefetch(sbase + ((c + 1) & 1) * MT_STAGE,
                        Ah, Al, Bh, Bl, m0, n0, (c + 1) << 6, K, tid);
            cp_wait<1>();
        } else {
            cp_wait<0>();
        }
        __syncthreads();

        const uint32_t sA = sbase + (c & 1) * MT_STAGE;
        const uint32_t sB = sA + 2 * MT_TILE;

        const int a_row = wm * 64 + (lane & 15);
        const int a_sg  = lane >> 4;
        const int b_row = wn * 32 + ((lane >> 4) << 3) + (lane & 7);
        const int b_sg  = (lane >> 3) & 1;

#pragma unroll
        for (int ks = 0; ks < 4; ++ks) {
            uint32_t ah[4][4], al[4][4], bh[2][4], bl[2][4];
#pragma unroll
            for (int i = 0; i < 4; ++i) {
                uint32_t off = swz((a_row + i * 16) * 128 + (2 * ks + a_sg) * 16);
                LDSM_X4(ah[i], sA + off);
                LDSM_X4(al[i], sA + MT_TILE + off);
            }
#pragma unroll
            for (int jp = 0; jp < 2; ++jp) {
                uint32_t off = swz((b_row + jp * 16) * 128 + (2 * ks + b_sg) * 16);
                LDSM_X4(bh[jp], sB + off);
                LDSM_X4(bl[jp], sB + MT_TILE + off);
            }
#pragma unroll
            for (int i = 0; i < 4; ++i)
#pragma unroll
                for (int j = 0; j < 4; ++j) {
                    uint32_t b0h = bh[j >> 1][(j & 1) * 2];
                    uint32_t b1h = bh[j >> 1][(j & 1) * 2 + 1];
                    uint32_t b0l = bl[j >> 1][(j & 1) * 2];
                    uint32_t b1l = bl[j >> 1][(j & 1) * 2 + 1];
                    mma_bf16(acc[i][j], ah[i], b0h, b1h);
                    mma_bf16(acc[i][j], ah[i], b0l, b1l);
                    mma_bf16(acc[i][j], al[i], b0h, b1h);
                }
        }
        __syncthreads();
    }
}

// Fused QKV GEMM: B = [Wq;Wk;Wv] (6144 rows). Q,K -> fp32; V -> bf16 hi/lo.
__global__ __launch_bounds__(256) void gemm_qkv_kernel(
    const __nv_bfloat16* __restrict__ Ah, const __nv_bfloat16* __restrict__ Al,
    const __nv_bfloat16* __restrict__ Bh, const __nv_bfloat16* __restrict__ Bl,
    float* __restrict__ Qf, float* __restrict__ Kf,
    __nv_bfloat16* __restrict__ Vh, __nv_bfloat16* __restrict__ Vl, int K)
{
    extern __shared__ __align__(1024) char smc[];
    const uint32_t sbase = smem_u32(smc);
    const int tid  = threadIdx.x;
    const int wid  = tid >> 5;
    const int lane = tid & 31;
    const int m0 = blockIdx.y * 128;
    const int n0 = blockIdx.x * 128;

    float acc[4][4][4];
#pragma unroll
    for (int i = 0; i < 4; i++)
#pragma unroll
        for (int j = 0; j < 4; j++)
#pragma unroll
            for (int r = 0; r < 4; r++) acc[i][j][r] = 0.f;

    mt_mainloop(acc, sbase, Ah, Al, Bh, Bl, m0, n0, K, tid);

    const int wm = wid & 1, wn = wid >> 1;
#pragma unroll
    for (int i = 0; i < 4; ++i) {
        int row = m0 + wm * 64 + i * 16 + (lane >> 2);
#pragma unroll
        for (int j = 0; j < 4; ++j) {
            int col = n0 + wn * 32 + j * 8 + (lane & 3) * 2;
            int cc  = col & 2047;
            size_t o0 = (size_t)row * HID + cc;
            size_t o1 = (size_t)(row + 8) * HID + cc;
            if (col < 4096) {
                float* dst = (col < 2048) ? Qf : Kf;
                *(float2*)(dst + o0) = make_float2(acc[i][j][0], acc[i][j][1]);
                *(float2*)(dst + o1) = make_float2(acc[i][j][2], acc[i][j][3]);
            } else {
                uint32_t h0, l0, h1, l1;
                pack_hl(acc[i][j][0], acc[i][j][1], h0, l0);
                pack_hl(acc[i][j][2], acc[i][j][3], h1, l1);
                *(uint32_t*)(Vh + o0) = h0; *(uint32_t*)(Vl + o0) = l0;
                *(uint32_t*)(Vh + o1) = h1; *(uint32_t*)(Vl + o1) = l1;
            }
        }
    }
}

// Plain GEMM (fp32 out): used for the final Wo projection.
__global__ __launch_bounds__(256) void gemm_mma_kernel(
    const __nv_bfloat16* __restrict__ Ah, const __nv_bfloat16* __restrict__ Al,
    const __nv_bfloat16* __restrict__ Bh, const __nv_bfloat16* __restrict__ Bl,
    float* __restrict__ C, int M, int N, int K)
{
    extern __shared__ __align__(1024) char smc[];
    const uint32_t sbase = smem_u32(smc);
    const int tid  = threadIdx.x;
    const int wid  = tid >> 5;
    const int lane = tid & 31;
    const int m0 = blockIdx.y * 128;
    const int n0 = blockIdx.x * 128;

    float acc[4][4][4];
#pragma unroll
    for (int i = 0; i < 4; i++)
#pragma unroll
        for (int j = 0; j < 4; j++)
#pragma unroll
            for (int r = 0; r < 4; r++) acc[i][j][r] = 0.f;

    mt_mainloop(acc, sbase, Ah, Al, Bh, Bl, m0, n0, K, tid);

    const int wm = wid & 1, wn = wid >> 1;
#pragma unroll
    for (int i = 0; i < 4; ++i) {
        int row = m0 + wm * 64 + i * 16 + (lane >> 2);
#pragma unroll
        for (int j = 0; j < 4; ++j) {
            int col = n0 + wn * 32 + j * 8 + (lane & 3) * 2;
            *(float2*)(C + (size_t)row * N + col) =
                make_float2(acc[i][j][0], acc[i][j][1]);
            *(float2*)(C + (size_t)(row + 8) * N + col) =
                make_float2(acc[i][j][2], acc[i][j][3]);
        }
    }
}

// ---------------- RoPE + bf16 hi/lo split (Q pre-scaled by scale*log2e) -----
__global__ void rope_split_kernel(const float* __restrict__ Q,
                                  const float* __restrict__ K,
                                  const int* __restrict__ pos,
                                  __nv_bfloat16* __restrict__ Qh,
                                  __nv_bfloat16* __restrict__ Ql,
                                  __nv_bfloat16* __restrict__ Kh,
                                  __nv_bfloat16* __restrict__ Kl)
{
    int s = blockIdx.x;
    int t = threadIdx.x;          // 1024 threads: (h, d<64)
    int h = t >> 6;
    int d = t & 63;

    const float QSC = (float)(0.08838834764831845 * 1.4426950408889634);

    float tp = (float)(pos[s] - g_minpos);
    float invf = (float)exp(-log(10000.0) * ((double)(2 * d) / 128.0));
    float ang = tp * invf;
    float c, sn;
    sincosf(ang, &sn, &c);

    size_t base = (size_t)s * HID + h * DHEAD;
    float q1 = Q[base + d], q2 = Q[base + d + 64];
    float k1 = K[base + d], k2 = K[base + d + 64];
    float qa = (q1 * c - q2 * sn) * QSC, qb = (q2 * c + q1 * sn) * QSC;
    float ka = k1 * c - k2 * sn, kb = k2 * c + k1 * sn;

    __nv_bfloat16 hq;
    hq = __float2bfloat16(qa); Qh[base + d] = hq;
    Ql[base + d]      = __float2bfloat16(qa - __bfloat162float(hq));
    hq = __float2bfloat16(qb); Qh[base + d + 64] = hq;
    Ql[base + d + 64] = __float2bfloat16(qb - __bfloat162float(hq));
    hq = __float2bfloat16(ka); Kh[base + d] = hq;
    Kl[base + d]      = __float2bfloat16(ka - __bfloat162float(hq));
    hq = __float2bfloat16(kb); Kh[base + d + 64] = hq;
    Kl[base + d + 64] = __float2bfloat16(kb - __bfloat162float(hq));
}

// ---------------- tensor-core flash attention --------------------------------
// Scores arrive pre-scaled in log2 domain (Q carries scale*log2e): softmax via
// ex2.approx only. Causal mask = add of -1e9*log2e (exact 0 after exp2).
// Output written directly as bf16 hi/lo (feeds the Wo GEMM).
#define AT_SQ  0
#define AT_SK  65536
#define AT_SV  131072
#define AT_SMEM 196608

__device__ __forceinline__ void at_prefetch_kv(
    uint32_t sb, int stage, const __nv_bfloat16* Kh, const __nv_bfloat16* Kl,
    const __nv_bfloat16* Vh, const __nv_bfloat16* Vl,
    int k0, int h, int tid)
{
    const uint32_t sK = sb + AT_SK + stage * 32768;
    const uint32_t sV = sb + AT_SV + stage * 32768;
#pragma unroll
    for (int i = 0; i < 8; ++i) {
        int idx = tid + i * 256;
        int hl = idx >> 10, rem = idx & 1023;
        int r = rem >> 4, dc = rem & 15;
        uint32_t sa = sK + hl * 16384 + (dc >> 3) * 8192
                    + swz(r * 128 + (dc & 7) * 16);
        const __nv_bfloat16* g = hl ? Kl : Kh;
        cp16(sa, g + (size_t)(k0 + r) * HID + h * DHEAD + dc * 8);
    }
#pragma unroll
    for (int i = 0; i < 8; ++i) {
        int idx = tid + i * 256;
        int hl = idx >> 10, rem = idx & 1023;
        int r = rem >> 4, dc = rem & 15;
        uint32_t sa = sV + hl * 16384 + (dc >> 3) * 8192
                    + swz(r * 128 + (dc & 7) * 16);
        const __nv_bfloat16* g = hl ? Vl : Vh;
        cp16(sa, g + (size_t)(k0 + r) * HID + h * DHEAD + dc * 8);
    }
    cp_commit();
}

__global__ __launch_bounds__(256) void attn_mma_kernel(
    const __nv_bfloat16* __restrict__ Qh, const __nv_bfloat16* __restrict__ Ql,
    const __nv_bfloat16* __restrict__ Kh, const __nv_bfloat16* __restrict__ Kl,
    const __nv_bfloat16* __restrict__ Vh, const __nv_bfloat16* __restrict__ Vl,
    __nv_bfloat16* __restrict__ Oh, __nv_bfloat16* __restrict__ Ol)
{
    extern __shared__ __align__(1024) char smb[];
    const uint32_t sb = smem_u32(smb);
    const int tid  = threadIdx.x;
    const int wid  = tid >> 5;
    const int lane = tid & 31;
    const int qb = (int)(gridDim.x - 1 - blockIdx.x);   // big blocks first
    const int h  = blockIdx.y;
    const int q0 = qb * 128;
    const int nkb = 2 * qb + 2;
    const float MASKC = -1.4426950e9f;                  // -1e9 * log2(e)

    // Q tile (hi/lo), loaded once
    {
#pragma unroll
        for (int i = 0; i < 16; ++i) {
            int idx = tid + i * 256;
            int hl = idx >> 11, rem = idx & 2047;
            int r = rem >> 4, dc = rem & 15;
            uint32_t sa = sb + AT_SQ + hl * 32768 + (dc >> 3) * 16384
                        + swz(r * 128 + (dc & 7) * 16);
            const __nv_bfloat16* g = hl ? Ql : Qh;
            cp16(sa, g + (size_t)(q0 + r) * HID + h * DHEAD + dc * 8);
        }
    }
    at_prefetch_kv(sb, 0, Kh, Kl, Vh, Vl, 0, h, tid);

    float o[16][4];
#pragma unroll
    for (int t = 0; t < 16; ++t)
#pragma unroll
        for (int r = 0; r < 4; ++r) o[t][r] = 0.f;
    float m0r = -INFINITY, m1r = -INFINITY, l0r = 0.f, l1r = 0.f;

    const int qrow0 = q0 + wid * 16 + (lane >> 2);
    const int qrow1 = qrow0 + 8;

    for (int c = 0; c < nkb; ++c) {
        if (c + 1 < nkb) {
            at_prefetch_kv(sb, (c + 1) & 1, Kh, Kl, Vh, Vl, (c + 1) * 64, h, tid);
            cp_wait<1>();
        } else {
            cp_wait<0>();
        }
        __syncthreads();

        const uint32_t sK = sb + AT_SK + (c & 1) * 32768;
        const uint32_t sV = sb + AT_SV + (c & 1) * 32768;
        const int k0 = c * 64;

        // ---- S = Q K^T (already in scale*log2e domain) ----
        float sacc[8][4];
#pragma unroll
        for (int j = 0; j < 8; ++j)
#pragma unroll
            for (int r = 0; r < 4; ++r) sacc[j][r] = 0.f;

#pragma unroll
        for (int ks = 0; ks < 8; ++ks) {
            const int kh = ks >> 2, sg = ks & 3;
            uint32_t ah[4], al[4];
            uint32_t qoff = kh * 16384 +
                swz((wid * 16 + (lane & 15)) * 128 + (2 * sg + (lane >> 4)) * 16);
            LDSM_X4(ah, sb + AT_SQ + qoff);
            LDSM_X4(al, sb + AT_SQ + 32768 + qoff);
#pragma unroll
            for (int ng = 0; ng < 4; ++ng) {
                uint32_t bh[4], bl[4];
                uint32_t koff = kh * 8192 +
                    swz((ng * 16 + ((lane >> 4) << 3) + (lane & 7)) * 128 +
                        (2 * sg + ((lane >> 3) & 1)) * 16);
                LDSM_X4(bh, sK + koff);
                LDSM_X4(bl, sK + 16384 + koff);
                mma_bf16(sacc[2 * ng],     ah, bh[0], bh[1]);
                mma_bf16(sacc[2 * ng],     ah, bl[0], bl[1]);
                mma_bf16(sacc[2 * ng],     al, bh[0], bh[1]);
                mma_bf16(sacc[2 * ng + 1], ah, bh[2], bh[3]);
                mma_bf16(sacc[2 * ng + 1], ah, bl[2], bl[3]);
                mma_bf16(sacc[2 * ng + 1], al, bh[2], bh[3]);
            }
        }

        // ---- causal mask (diagonal blocks only) + online softmax in exp2 ----
        if ((k0 + 63) > q0) {
#pragma unroll
            for (int j = 0; j < 8; ++j) {
                int col = k0 + j * 8 + (lane & 3) * 2;
                if (col     > qrow0) sacc[j][0] += MASKC;
                if (col + 1 > qrow0) sacc[j][1] += MASKC;
                if (col     > qrow1) sacc[j][2] += MASKC;
                if (col + 1 > qrow1) sacc[j][3] += MASKC;
            }
        }
        float mx0 = -INFINITY, mx1 = -INFINITY;
#pragma unroll
        for (int j = 0; j < 8; ++j) {
            mx0 = fmaxf(mx0, fmaxf(sacc[j][0], sacc[j][1]));
            mx1 = fmaxf(mx1, fmaxf(sacc[j][2], sacc[j][3]));
        }
        mx0 = fmaxf(mx0, __shfl_xor_sync(0xffffffffu, mx0, 1));
        mx0 = fmaxf(mx0, __shfl_xor_sync(0xffffffffu, mx0, 2));
        mx1 = fmaxf(mx1, __shfl_xor_sync(0xffffffffu, mx1, 1));
        mx1 = fmaxf(mx1, __shfl_xor_sync(0xffffffffu, mx1, 2));

        float mn0 = fmaxf(m0r, mx0), mn1 = fmaxf(m1r, mx1);
        float fac0 = ex2(m0r - mn0), fac1 = ex2(m1r - mn1);
        m0r = mn0; m1r = mn1;

        float ls0 = 0.f, ls1 = 0.f;
#pragma unroll
        for (int j = 0; j < 8; ++j) {
            sacc[j][0] = ex2(sacc[j][0] - mn0);
            sacc[j][1] = ex2(sacc[j][1] - mn0);
            sacc[j][2] = ex2(sacc[j][2] - mn1);
            sacc[j][3] = ex2(sacc[j][3] - mn1);
            ls0 += sacc[j][0] + sacc[j][1];
            ls1 += sacc[j][2] + sacc[j][3];
        }
        ls0 += __shfl_xor_sync(0xffffffffu, ls0, 1);
        ls0 += __shfl_xor_sync(0xffffffffu, ls0, 2);
        ls1 += __shfl_xor_sync(0xffffffffu, ls1, 1);
        ls1 += __shfl_xor_sync(0xffffffffu, ls1, 2);
        l0r = l0r * fac0 + ls0;
        l1r = l1r * fac1 + ls1;

#pragma unroll
        for (int t = 0; t < 16; ++t) {
            o[t][0] *= fac0; o[t][1] *= fac0;
            o[t][2] *= fac1; o[t][3] *= fac1;
        }

        // ---- O += P V ----
#pragma unroll
        for (int ks = 0; ks < 4; ++ks) {
            uint32_t ph[4], pl[4];
            pack_hl(sacc[2 * ks][0],     sacc[2 * ks][1],     ph[0], pl[0]);
            pack_hl(sacc[2 * ks][2],     sacc[2 * ks][3],     ph[1], pl[1]);
            pack_hl(sacc[2 * ks + 1][0], sacc[2 * ks + 1][1], ph[2], pl[2]);
            pack_hl(sacc[2 * ks + 1][2], sacc[2 * ks + 1][3], ph[3], pl[3]);
#pragma unroll
            for (int ng = 0; ng < 8; ++ng) {
                uint32_t vh[4], vl[4];
                uint32_t voff = (ng >> 2) * 8192 +
                    swz((ks * 16 + (lane & 15)) * 128 +
                        (ng & 3) * 32 + (lane >> 4) * 16);
                LDSM_X4T(vh, sV + voff);
                LDSM_X4T(vl, sV + 16384 + voff);
                mma_bf16(o[2 * ng],     ph, vh[0], vh[1]);
                mma_bf16(o[2 * ng],     ph, vl[0], vl[1]);
                mma_bf16(o[2 * ng],     pl, vh[0], vh[1]);
                mma_bf16(o[2 * ng + 1], ph, vh[2], vh[3]);
                mma_bf16(o[2 * ng + 1], ph, vl[2], vl[3]);
                mma_bf16(o[2 * ng + 1], pl, vh[2], vh[3]);
            }
        }
        __syncthreads();
    }

    // ---- normalize + write bf16 hi/lo directly (feeds Wo GEMM) ----
    float inv0 = 1.f / l0r, inv1 = 1.f / l1r;
#pragma unroll
    for (int t = 0; t < 16; ++t) {
        size_t col = h * DHEAD + t * 8 + (lane & 3) * 2;
        size_t o0 = (size_t)qrow0 * HID + col;
        size_t o1 = (size_t)qrow1 * HID + col;
        uint32_t h0, l0, h1, l1;
        pack_hl(o[t][0] * inv0, o[t][1] * inv0, h0, l0);
        pack_hl(o[t][2] * inv1, o[t][3] * inv1, h1, l1);
        *(uint32_t*)(Oh + o0) = h0; *(uint32_t*)(Ol + o0) = l0;
        *(uint32_t*)(Oh + o1) = h1; *(uint32_t*)(Ol + o1) = l1;
    }
}

// ---------------- launch ----------------------------------------------------
extern "C" void kernel_launch(void* const* d_in, const int* in_sizes, int n_in,
                              void* d_out, int out_size)
{
    const float* X    = (const float*)d_in[0];
    const int*   pos  = (const int*)d_in[2];   // JAX x64 disabled: int32
    const float* Wq   = (const float*)d_in[3];
    const float* Wk   = (const float*)d_in[4];
    const float* Wv   = (const float*)d_in[5];
    const float* Wo   = (const float*)d_in[6];
    float*       out  = (float*)d_out;

    float *Qp, *Kp;
    __nv_bfloat16 *Xh, *Xl, *Wh, *Wl, *Aoh, *Aol;
    __nv_bfloat16 *Qbh, *Qbl, *Kbh, *Kbl, *Vbh, *Vbl;
    cudaGetSymbolAddress((void**)&Qp, g_Q);
    cudaGetSymbolAddress((void**)&Kp, g_K);
    cudaGetSymbolAddress((void**)&Xh, g_Xh);
    cudaGetSymbolAddress((void**)&Xl, g_Xl);
    cudaGetSymbolAddress((void**)&Wh, g_Wh);
    cudaGetSymbolAddress((void**)&Wl, g_Wl);
    cudaGetSymbolAddress((void**)&Aoh, g_Aoh);
    cudaGetSymbolAddress((void**)&Aol, g_Aol);
    cudaGetSymbolAddress((void**)&Qbh, g_Qbh);
    cudaGetSymbolAddress((void**)&Qbl, g_Qbl);
    cudaGetSymbolAddress((void**)&Kbh, g_Kbh);
    cudaGetSymbolAddress((void**)&Kbl, g_Kbl);
    cudaGetSymbolAddress((void**)&Vbh, g_Vbh);
    cudaGetSymbolAddress((void**)&Vbl, g_Vbl);

    minpos_kernel<<<1, 256>>>(pos, S_LEN);

    const int xn4 = (S_LEN * HID) / 4;
    const int wn4 = (HID * HID) / 4;
    split_kernel<<<xn4 / 256, 256>>>(X, Xh, Xl, xn4);
    split_kernel<<<wn4 / 256, 256>>>(Wq, Wh + 0 * W_SZ, Wl + 0 * W_SZ, wn4);
    split_kernel<<<wn4 / 256, 256>>>(Wk, Wh + 1 * W_SZ, Wl + 1 * W_SZ, wn4);
    split_kernel<<<wn4 / 256, 256>>>(Wv, Wh + 2 * W_SZ, Wl + 2 * W_SZ, wn4);
    split_kernel<<<wn4 / 256, 256>>>(Wo, Wh + 3 * W_SZ, Wl + 3 * W_SZ, wn4);

    cudaFuncSetAttribute(gemm_qkv_kernel,
                         cudaFuncAttributeMaxDynamicSharedMemorySize, MT_SMEM);
    cudaFuncSetAttribute(gemm_mma_kernel,
                         cudaFuncAttributeMaxDynamicSharedMemorySize, MT_SMEM);

    // fused QKV: B has 6144 rows (Wq|Wk|Wv contiguous in g_Wh/g_Wl)
    dim3 gq(3 * HID / 128, S_LEN / 128);       // (48, 32)
    gemm_qkv_kernel<<<gq, 256, MT_SMEM>>>(Xh, Xl, Wh, Wl,
                                          Qp, Kp, Vbh, Vbl, HID);

    rope_split_kernel<<<S_LEN, 1024>>>(Qp, Kp, pos, Qbh, Qbl, Kbh, Kbl);

    cudaFuncSetAttribute(attn_mma_kernel,
                         cudaFuncAttributeMaxDynamicSharedMemorySize, AT_SMEM);
    dim3 ag(S_LEN / 128, NHEAD);               // (32, 16)
    attn_mma_kernel<<<ag, 256, AT_SMEM>>>(Qbh, Qbl, Kbh, Kbl, Vbh, Vbl,
                                          Aoh, Aol);

    dim3 gg(HID / 128, S_LEN / 128);           // (16, 32)
    gemm_mma_kernel<<<gg, 256, MT_SMEM>>>(Aoh, Aol, Wh + 3 * W_SZ, Wl + 3 * W_SZ,
                                          out, S_LEN, HID, HID);
}

// round 14
// speedup vs baseline: 4.4388x; 1.3103x over previous
#include <cuda_runtime.h>
#include <cuda_fp16.h>
#include <math.h>
#include <stdint.h>

#define S_LEN 4096
#define HID   2048
#define NHEAD 16
#define DHEAD 128
#define W_SZ  ((size_t)HID * HID)

// ---------------- scratch (device globals; no allocations allowed) ----------
__device__ float g_Q[(size_t)S_LEN * HID];
__device__ float g_K[(size_t)S_LEN * HID];
__device__ __align__(16) __half g_Xh[(size_t)S_LEN * HID];      // X fp16 (A-side single)
__device__ __align__(16) __half g_Wh[4 * W_SZ];                 // W hi (B-side)
__device__ __align__(16) __half g_Wl[4 * W_SZ];                 // W lo
__device__ __align__(16) __half g_Aoh[(size_t)S_LEN * HID];     // attn out fp16 single
__device__ __align__(16) __half g_Qbh[(size_t)S_LEN * HID];     // rope'd Q fp16 (scaled)
__device__ __align__(16) __half g_Kbh[(size_t)S_LEN * HID];     // rope'd K hi
__device__ __align__(16) __half g_Kbl[(size_t)S_LEN * HID];     // rope'd K lo
__device__ __align__(16) __half g_Vbh[(size_t)S_LEN * HID];     // V hi
__device__ __align__(16) __half g_Vbl[(size_t)S_LEN * HID];     // V lo
__device__ int g_minpos;

// ---------------- PTX helpers (all sm_80-era: valid on compute_103) ---------
__device__ __forceinline__ uint32_t smem_u32(const void* p) {
    uint32_t a;
    asm("{ .reg .u64 t; cvta.to.shared.u64 t, %1; cvt.u32.u64 %0, t; }"
        : "=r"(a) : "l"(p));
    return a;
}

__device__ __forceinline__ void cp16(uint32_t saddr, const void* g) {
    asm volatile("cp.async.cg.shared.global [%0], [%1], 16;"
                 :: "r"(saddr), "l"(g) : "memory");
}
__device__ __forceinline__ void cp_commit() {
    asm volatile("cp.async.commit_group;" ::: "memory");
}
template <int N>
__device__ __forceinline__ void cp_wait() {
    asm volatile("cp.async.wait_group %0;" :: "n"(N) : "memory");
}

#define LDSM_X4(r, addr) \
    asm volatile("ldmatrix.sync.aligned.m8n8.x4.shared.b16 {%0,%1,%2,%3}, [%4];" \
                 : "=r"((r)[0]), "=r"((r)[1]), "=r"((r)[2]), "=r"((r)[3]) \
                 : "r"(addr))

#define LDSM_X4T(r, addr) \
    asm volatile("ldmatrix.sync.aligned.m8n8.x4.trans.shared.b16 {%0,%1,%2,%3}, [%4];" \
                 : "=r"((r)[0]), "=r"((r)[1]), "=r"((r)[2]), "=r"((r)[3]) \
                 : "r"(addr))

__device__ __forceinline__ void mma_f16(float* c, const uint32_t* a,
                                        uint32_t b0, uint32_t b1) {
    asm volatile(
        "mma.sync.aligned.m16n8k16.row.col.f32.f16.f16.f32 "
        "{%0,%1,%2,%3}, {%4,%5,%6,%7}, {%8,%9}, {%0,%1,%2,%3};"
        : "+f"(c[0]), "+f"(c[1]), "+f"(c[2]), "+f"(c[3])
        : "r"(a[0]), "r"(a[1]), "r"(a[2]), "r"(a[3]), "r"(b0), "r"(b1));
}

__device__ __forceinline__ uint32_t swz(uint32_t boff) {   // SW128-style
    return boff ^ ((boff >> 3) & 0x70);
}

__device__ __forceinline__ uint32_t pack_h2(float x, float y) {
    __half2 h = __floats2half2_rn(x, y);
    return *reinterpret_cast<uint32_t*>(&h);
}

__device__ __forceinline__ void pack_hl_f16(float x, float y,
                                            uint32_t& h, uint32_t& l) {
    __half2 hh = __floats2half2_rn(x, y);
    h = *reinterpret_cast<uint32_t*>(&hh);
    __half2 ll = __floats2half2_rn(x - __low2float(hh), y - __high2float(hh));
    l = *reinterpret_cast<uint32_t*>(&ll);
}

__device__ __forceinline__ float ex2(float x) {
    float y;
    asm("ex2.approx.ftz.f32 %0, %1;" : "=f"(y) : "f"(x));
    return y;
}

// ---------------- min(position_ids)  (JAX demotes int64->int32) -------------
__global__ void minpos_kernel(const int* __restrict__ pos, int n)
{
    __shared__ int sm[256];
    int v = 0x7fffffff;
    for (int i = threadIdx.x; i < n; i += 256) {
        int p = pos[i];
        v = (p < v) ? p : v;
    }
    sm[threadIdx.x] = v;
    __syncthreads();
    for (int s = 128; s > 0; s >>= 1) {
        if (threadIdx.x < s) {
            int o = sm[threadIdx.x + s];
            if (o < sm[threadIdx.x]) sm[threadIdx.x] = o;
        }
        __syncthreads();
    }
    if (threadIdx.x == 0) g_minpos = sm[0];
}

// ---------------- fp32 -> fp16 hi/lo (B-side) and fp32 -> fp16 (A-side) -----
__global__ void split_w_kernel(const float* __restrict__ x,
                               __half* __restrict__ hi,
                               __half* __restrict__ lo, int n4)
{
    int i = blockIdx.x * blockDim.x + threadIdx.x;
    if (i >= n4) return;
    float4 v = ((const float4*)x)[i];
    uint32_t h0, l0, h1, l1;
    pack_hl_f16(v.x, v.y, h0, l0);
    pack_hl_f16(v.z, v.w, h1, l1);
    ((uint2*)hi)[i] = make_uint2(h0, h1);
    ((uint2*)lo)[i] = make_uint2(l0, l1);
}

__global__ void conv_h_kernel(const float* __restrict__ x,
                              __half* __restrict__ h, int n4)
{
    int i = blockIdx.x * blockDim.x + threadIdx.x;
    if (i >= n4) return;
    float4 v = ((const float4*)x)[i];
    ((uint2*)h)[i] = make_uint2(pack_h2(v.x, v.y), pack_h2(v.z, v.w));
}

// ---------------- mma.sync fp16 2-pass GEMM core: C = A * B^T ---------------
// A fp16 single; B fp16 hi/lo. Tile 128x128, K chunks of 64. 8 warps (2m x 4n).
#define MT_TILE  16384                       // 128 rows x 64 fp16 (128B rows)
#define MT_STAGE (3 * MT_TILE)               // A, Bh, Bl = 48K
#define MT_SMEM  (2 * MT_STAGE)              // 98304 B

__device__ __forceinline__ void mt_prefetch(
    uint32_t st, const __half* A,
    const __half* Bh, const __half* Bl,
    int m0, int n0, int k0, int K, int tid)
{
#pragma unroll
    for (int i = 0; i < 4; ++i) {
        int idx = tid + i * 256;             // 0..1023
        int r   = idx >> 3;
        int s   = idx & 7;
        uint32_t sw = swz(r * 128 + s * 16);
        size_t ga = (size_t)(m0 + r) * K + k0 + s * 8;
        size_t gb = (size_t)(n0 + r) * K + k0 + s * 8;
        cp16(st + sw,               A  + ga);
        cp16(st + MT_TILE + sw,     Bh + gb);
        cp16(st + 2 * MT_TILE + sw, Bl + gb);
    }
    cp_commit();
}

__device__ __forceinline__ void mt_mainloop(
    float acc[4][4][4], uint32_t sbase,
    const __half* A, const __half* Bh, const __half* Bl,
    int m0, int n0, int K, int tid)
{
    const int wid  = tid >> 5;
    const int lane = tid & 31;
    const int wm   = wid & 1;
    const int wn   = wid >> 1;

    const int nch = K >> 6;
    mt_prefetch(sbase, A, Bh, Bl, m0, n0, 0, K, tid);

    for (int c = 0; c < nch; ++c) {
        if (c + 1 < nch) {
            mt_prefetch(sbase + ((c + 1) & 1) * MT_STAGE,
                        A, Bh, Bl, m0, n0, (c + 1) << 6, K, tid);
            cp_wait<1>();
        } else {
            cp_wait<0>();
        }
        __syncthreads();

        const uint32_t sA = sbase + (c & 1) * MT_STAGE;
        const uint32_t sB = sA + MT_TILE;

        const int a_row = wm * 64 + (lane & 15);
        const int a_sg  = lane >> 4;
        const int b_row = wn * 32 + ((lane >> 4) << 3) + (lane & 7);
        const int b_sg  = (lane >> 3) & 1;

#pragma unroll
        for (int ks = 0; ks < 4; ++ks) {
            uint32_t ah[4][4], bh[2][4], bl[2][4];
#pragma unroll
            for (int i = 0; i < 4; ++i) {
                uint32_t off = swz((a_row + i * 16) * 128 + (2 * ks + a_sg) * 16);
                LDSM_X4(ah[i], sA + off);
            }
#pragma unroll
            for (int jp = 0; jp < 2; ++jp) {
                uint32_t off = swz((b_row + jp * 16) * 128 + (2 * ks + b_sg) * 16);
                LDSM_X4(bh[jp], sB + off);
                LDSM_X4(bl[jp], sB + MT_TILE + off);
            }
#pragma unroll
            for (int i = 0; i < 4; ++i)
#pragma unroll
                for (int j = 0; j < 4; ++j) {
                    mma_f16(acc[i][j], ah[i],
                            bh[j >> 1][(j & 1) * 2], bh[j >> 1][(j & 1) * 2 + 1]);
                    mma_f16(acc[i][j], ah[i],
                            bl[j >> 1][(j & 1) * 2], bl[j >> 1][(j & 1) * 2 + 1]);
                }
        }
        __syncthreads();
    }
}

// Fused QKV GEMM: B = [Wq;Wk;Wv] (6144 rows). Q,K -> fp32; V -> fp16 hi/lo.
__global__ __launch_bounds__(256) void gemm_qkv_kernel(
    const __half* __restrict__ A,
    const __half* __restrict__ Bh, const __half* __restrict__ Bl,
    float* __restrict__ Qf, float* __restrict__ Kf,
    __half* __restrict__ Vh, __half* __restrict__ Vl, int K)
{
    extern __shared__ __align__(1024) char smc[];
    const uint32_t sbase = smem_u32(smc);
    const int tid  = threadIdx.x;
    const int wid  = tid >> 5;
    const int lane = tid & 31;
    const int m0 = blockIdx.y * 128;
    const int n0 = blockIdx.x * 128;

    float acc[4][4][4];
#pragma unroll
    for (int i = 0; i < 4; i++)
#pragma unroll
        for (int j = 0; j < 4; j++)
#pragma unroll
            for (int r = 0; r < 4; r++) acc[i][j][r] = 0.f;

    mt_mainloop(acc, sbase, A, Bh, Bl, m0, n0, K, tid);

    const int wm = wid & 1, wn = wid >> 1;
#pragma unroll
    for (int i = 0; i < 4; ++i) {
        int row = m0 + wm * 64 + i * 16 + (lane >> 2);
#pragma unroll
        for (int j = 0; j < 4; ++j) {
            int col = n0 + wn * 32 + j * 8 + (lane & 3) * 2;
            int cc  = col & 2047;
            size_t o0 = (size_t)row * HID + cc;
            size_t o1 = (size_t)(row + 8) * HID + cc;
            if (col < 4096) {
                float* dst = (col < 2048) ? Qf : Kf;
                *(float2*)(dst + o0) = make_float2(acc[i][j][0], acc[i][j][1]);
                *(float2*)(dst + o1) = make_float2(acc[i][j][2], acc[i][j][3]);
            } else {
                uint32_t h0, l0, h1, l1;
                pack_hl_f16(acc[i][j][0], acc[i][j][1], h0, l0);
                pack_hl_f16(acc[i][j][2], acc[i][j][3], h1, l1);
                *(uint32_t*)(Vh + o0) = h0; *(uint32_t*)(Vl + o0) = l0;
                *(uint32_t*)(Vh + o1) = h1; *(uint32_t*)(Vl + o1) = l1;
            }
        }
    }
}

// Plain GEMM (fp32 out): final Wo projection.
__global__ __launch_bounds__(256) void gemm_mma_kernel(
    const __half* __restrict__ A,
    const __half* __restrict__ Bh, const __half* __restrict__ Bl,
    float* __restrict__ C, int M, int N, int K)
{
    extern __shared__ __align__(1024) char smc[];
    const uint32_t sbase = smem_u32(smc);
    const int tid  = threadIdx.x;
    const int wid  = tid >> 5;
    const int lane = tid & 31;
    const int m0 = blockIdx.y * 128;
    const int n0 = blockIdx.x * 128;

    float acc[4][4][4];
#pragma unroll
    for (int i = 0; i < 4; i++)
#pragma unroll
        for (int j = 0; j < 4; j++)
#pragma unroll
            for (int r = 0; r < 4; r++) acc[i][j][r] = 0.f;

    mt_mainloop(acc, sbase, A, Bh, Bl, m0, n0, K, tid);

    const int wm = wid & 1, wn = wid >> 1;
#pragma unroll
    for (int i = 0; i < 4; ++i) {
        int row = m0 + wm * 64 + i * 16 + (lane >> 2);
#pragma unroll
        for (int j = 0; j < 4; ++j) {
            int col = n0 + wn * 32 + j * 8 + (lane & 3) * 2;
            *(float2*)(C + (size_t)row * N + col) =
                make_float2(acc[i][j][0], acc[i][j][1]);
            *(float2*)(C + (size_t)(row + 8) * N + col) =
                make_float2(acc[i][j][2], acc[i][j][3]);
        }
    }
}

// ---------------- RoPE + fp16 convert (Q scaled by scale*log2e; K hi/lo) ----
__global__ void rope_split_kernel(const float* __restrict__ Q,
                                  const float* __restrict__ K,
                                  const int* __restrict__ pos,
                                  __half* __restrict__ Qh,
                                  __half* __restrict__ Kh,
                                  __half* __restrict__ Kl)
{
    int s = blockIdx.x;
    int t = threadIdx.x;          // 1024 threads: (h, d<64)
    int h = t >> 6;
    int d = t & 63;

    const float QSC = (float)(0.08838834764831845 * 1.4426950408889634);

    float tp = (float)(pos[s] - g_minpos);
    float invf = (float)exp(-log(10000.0) * ((double)(2 * d) / 128.0));
    float ang = tp * invf;
    float c, sn;
    sincosf(ang, &sn, &c);

    size_t base = (size_t)s * HID + h * DHEAD;
    float q1 = Q[base + d], q2 = Q[base + d + 64];
    float k1 = K[base + d], k2 = K[base + d + 64];
    float qa = (q1 * c - q2 * sn) * QSC, qb = (q2 * c + q1 * sn) * QSC;
    float ka = k1 * c - k2 * sn, kb = k2 * c + k1 * sn;

    Qh[base + d]      = __float2half(qa);
    Qh[base + d + 64] = __float2half(qb);
    __half kh;
    kh = __float2half(ka); Kh[base + d] = kh;
    Kl[base + d]      = __float2half(ka - __half2float(kh));
    kh = __float2half(kb); Kh[base + d + 64] = kh;
    Kl[base + d + 64] = __float2half(kb - __half2float(kh));
}

// ---------------- tensor-core flash attention (fp16 2-pass) ------------------
// Q fp16 single (pre-scaled, log2 domain); K,V fp16 hi/lo; P fp16 single.
// smem: Q 32K @0 | K stages 2x32K @32K | V stages 2x32K @96K = 160K.
#define AT_SQ  0
#define AT_SK  32768
#define AT_SV  98304
#define AT_SMEM 163840

__device__ __forceinline__ void at_prefetch_kv(
    uint32_t sb, int stage, const __half* Kh, const __half* Kl,
    const __half* Vh, const __half* Vl,
    int k0, int h, int tid)
{
    const uint32_t sK = sb + AT_SK + stage * 32768;
    const uint32_t sV = sb + AT_SV + stage * 32768;
#pragma unroll
    for (int i = 0; i < 8; ++i) {             // K: 2048 cp16 (hi + lo)
        int idx = tid + i * 256;
        int hl = idx >> 10, rem = idx & 1023;
        int r = rem >> 4, dc = rem & 15;
        uint32_t sa = sK + hl * 16384 + (dc >> 3) * 8192
                    + swz(r * 128 + (dc & 7) * 16);
        const __half* g = hl ? Kl : Kh;
        cp16(sa, g + (size_t)(k0 + r) * HID + h * DHEAD + dc * 8);
    }
#pragma unroll
    for (int i = 0; i < 8; ++i) {             // V: 2048 cp16 (hi + lo)
        int idx = tid + i * 256;
        int hl = idx >> 10, rem = idx & 1023;
        int r = rem >> 4, dc = rem & 15;
        uint32_t sa = sV + hl * 16384 + (dc >> 3) * 8192
                    + swz(r * 128 + (dc & 7) * 16);
        const __half* g = hl ? Vl : Vh;
        cp16(sa, g + (size_t)(k0 + r) * HID + h * DHEAD + dc * 8);
    }
    cp_commit();
}

__global__ __launch_bounds__(256) void attn_mma_kernel(
    const __half* __restrict__ Qh,
    const __half* __restrict__ Kh, const __half* __restrict__ Kl,
    const __half* __restrict__ Vh, const __half* __restrict__ Vl,
    __half* __restrict__ Oh)
{
    extern __shared__ __align__(1024) char smb[];
    const uint32_t sb = smem_u32(smb);
    const int tid  = threadIdx.x;
    const int wid  = tid >> 5;
    const int lane = tid & 31;
    const int qb = (int)(gridDim.x - 1 - blockIdx.x);   // big blocks first
    const int h  = blockIdx.y;
    const int q0 = qb * 128;
    const int nkb = 2 * qb + 2;
    const float MASKC = -1.4426950e9f;                  // -1e9 * log2(e)

    // Q tile (fp16 single), loaded once: 2048 cp16
    {
#pragma unroll
        for (int i = 0; i < 8; ++i) {
            int idx = tid + i * 256;
            int r = idx >> 4, dc = idx & 15;
            uint32_t sa = sb + AT_SQ + (dc >> 3) * 16384
                        + swz(r * 128 + (dc & 7) * 16);
            cp16(sa, Qh + (size_t)(q0 + r) * HID + h * DHEAD + dc * 8);
        }
    }
    at_prefetch_kv(sb, 0, Kh, Kl, Vh, Vl, 0, h, tid);

    float o[16][4];
#pragma unroll
    for (int t = 0; t < 16; ++t)
#pragma unroll
        for (int r = 0; r < 4; ++r) o[t][r] = 0.f;
    float m0r = -INFINITY, m1r = -INFINITY, l0r = 0.f, l1r = 0.f;

    const int qrow0 = q0 + wid * 16 + (lane >> 2);
    const int qrow1 = qrow0 + 8;

    for (int c = 0; c < nkb; ++c) {
        if (c + 1 < nkb) {
            at_prefetch_kv(sb, (c + 1) & 1, Kh, Kl, Vh, Vl, (c + 1) * 64, h, tid);
            cp_wait<1>();
        } else {
            cp_wait<0>();
        }
        __syncthreads();

        const uint32_t sK = sb + AT_SK + (c & 1) * 32768;
        const uint32_t sV = sb + AT_SV + (c & 1) * 32768;
        const int k0 = c * 64;

        // ---- S = Q K^T (2 passes: Qh*Kh + Qh*Kl) ----
        float sacc[8][4];
#pragma unroll
        for (int j = 0; j < 8; ++j)
#pragma unroll
            for (int r = 0; r < 4; ++r) sacc[j][r] = 0.f;

#pragma unroll
        for (int ks = 0; ks < 8; ++ks) {
            const int kh = ks >> 2, sg = ks & 3;
            uint32_t a[4];
            uint32_t qoff = kh * 16384 +
                swz((wid * 16 + (lane & 15)) * 128 + (2 * sg + (lane >> 4)) * 16);
            LDSM_X4(a, sb + AT_SQ + qoff);
#pragma unroll
            for (int ng = 0; ng < 4; ++ng) {
                uint32_t bh[4], bl[4];
                uint32_t koff = kh * 8192 +
                    swz((ng * 16 + ((lane >> 4) << 3) + (lane & 7)) * 128 +
                        (2 * sg + ((lane >> 3) & 1)) * 16);
                LDSM_X4(bh, sK + koff);
                LDSM_X4(bl, sK + 16384 + koff);
                mma_f16(sacc[2 * ng],     a, bh[0], bh[1]);
                mma_f16(sacc[2 * ng],     a, bl[0], bl[1]);
                mma_f16(sacc[2 * ng + 1], a, bh[2], bh[3]);
                mma_f16(sacc[2 * ng + 1], a, bl[2], bl[3]);
            }
        }

        // ---- causal mask (diagonal blocks only) + online softmax in exp2 ----
        if ((k0 + 63) > q0) {
#pragma unroll
            for (int j = 0; j < 8; ++j) {
                int col = k0 + j * 8 + (lane & 3) * 2;
                if (col     > qrow0) sacc[j][0] += MASKC;
                if (col + 1 > qrow0) sacc[j][1] += MASKC;
                if (col     > qrow1) sacc[j][2] += MASKC;
                if (col + 1 > qrow1) sacc[j][3] += MASKC;
            }
        }
        float mx0 = -INFINITY, mx1 = -INFINITY;
#pragma unroll
        for (int j = 0; j < 8; ++j) {
            mx0 = fmaxf(mx0, fmaxf(sacc[j][0], sacc[j][1]));
            mx1 = fmaxf(mx1, fmaxf(sacc[j][2], sacc[j][3]));
        }
        mx0 = fmaxf(mx0, __shfl_xor_sync(0xffffffffu, mx0, 1));
        mx0 = fmaxf(mx0, __shfl_xor_sync(0xffffffffu, mx0, 2));
        mx1 = fmaxf(mx1, __shfl_xor_sync(0xffffffffu, mx1, 1));
        mx1 = fmaxf(mx1, __shfl_xor_sync(0xffffffffu, mx1, 2));

        float mn0 = fmaxf(m0r, mx0), mn1 = fmaxf(m1r, mx1);
        float fac0 = ex2(m0r - mn0), fac1 = ex2(m1r - mn1);
        m0r = mn0; m1r = mn1;

        float ls0 = 0.f, ls1 = 0.f;
#pragma unroll
        for (int j = 0; j < 8; ++j) {
            sacc[j][0] = ex2(sacc[j][0] - mn0);
            sacc[j][1] = ex2(sacc[j][1] - mn0);
            sacc[j][2] = ex2(sacc[j][2] - mn1);
            sacc[j][3] = ex2(sacc[j][3] - mn1);
            ls0 += sacc[j][0] + sacc[j][1];
            ls1 += sacc[j][2] + sacc[j][3];
        }
        ls0 += __shfl_xor_sync(0xffffffffu, ls0, 1);
        ls0 += __shfl_xor_sync(0xffffffffu, ls0, 2);
        ls1 += __shfl_xor_sync(0xffffffffu, ls1, 1);
        ls1 += __shfl_xor_sync(0xffffffffu, ls1, 2);
        l0r = l0r * fac0 + ls0;
        l1r = l1r * fac1 + ls1;

#pragma unroll
        for (int t = 0; t < 16; ++t) {
            o[t][0] *= fac0; o[t][1] *= fac0;
            o[t][2] *= fac1; o[t][3] *= fac1;
        }

        // ---- O += P V (P fp16 single; 2 passes: P*Vh + P*Vl) ----
#pragma unroll
        for (int ks = 0; ks < 4; ++ks) {
            uint32_t p[4];
            p[0] = pack_h2(sacc[2 * ks][0],     sacc[2 * ks][1]);
            p[1] = pack_h2(sacc[2 * ks][2],     sacc[2 * ks][3]);
            p[2] = pack_h2(sacc[2 * ks + 1][0], sacc[2 * ks + 1][1]);
            p[3] = pack_h2(sacc[2 * ks + 1][2], sacc[2 * ks + 1][3]);
#pragma unroll
            for (int ng = 0; ng < 8; ++ng) {
                uint32_t vh[4], vl[4];
                uint32_t voff = (ng >> 2) * 8192 +
                    swz((ks * 16 + (lane & 15)) * 128 +
                        (ng & 3) * 32 + (lane >> 4) * 16);
                LDSM_X4T(vh, sV + voff);
                LDSM_X4T(vl, sV + 16384 + voff);
                mma_f16(o[2 * ng],     p, vh[0], vh[1]);
                mma_f16(o[2 * ng],     p, vl[0], vl[1]);
                mma_f16(o[2 * ng + 1], p, vh[2], vh[3]);
                mma_f16(o[2 * ng + 1], p, vl[2], vl[3]);
            }
        }
        __syncthreads();
    }

    // ---- normalize + write fp16 single (feeds Wo GEMM A-side) ----
    float inv0 = 1.f / l0r, inv1 = 1.f / l1r;
#pragma unroll
    for (int t = 0; t < 16; ++t) {
        size_t col = h * DHEAD + t * 8 + (lane & 3) * 2;
        *(uint32_t*)(Oh + (size_t)qrow0 * HID + col) =
            pack_h2(o[t][0] * inv0, o[t][1] * inv0);
        *(uint32_t*)(Oh + (size_t)qrow1 * HID + col) =
            pack_h2(o[t][2] * inv1, o[t][3] * inv1);
    }
}

// ---------------- launch ----------------------------------------------------
extern "C" void kernel_launch(void* const* d_in, const int* in_sizes, int n_in,
                              void* d_out, int out_size)
{
    const float* X    = (const float*)d_in[0];
    const int*   pos  = (const int*)d_in[2];   // JAX x64 disabled: int32
    const float* Wq   = (const float*)d_in[3];
    const float* Wk   = (const float*)d_in[4];
    const float* Wv   = (const float*)d_in[5];
    const float* Wo   = (const float*)d_in[6];
    float*       out  = (float*)d_out;

    float *Qp, *Kp;
    __half *Xh, *Wh, *Wl, *Aoh, *Qbh, *Kbh, *Kbl, *Vbh, *Vbl;
    cudaGetSymbolAddress((void**)&Qp, g_Q);
    cudaGetSymbolAddress((void**)&Kp, g_K);
    cudaGetSymbolAddress((void**)&Xh, g_Xh);
    cudaGetSymbolAddress((void**)&Wh, g_Wh);
    cudaGetSymbolAddress((void**)&Wl, g_Wl);
    cudaGetSymbolAddress((void**)&Aoh, g_Aoh);
    cudaGetSymbolAddress((void**)&Qbh, g_Qbh);
    cudaGetSymbolAddress((void**)&Kbh, g_Kbh);
    cudaGetSymbolAddress((void**)&Kbl, g_Kbl);
    cudaGetSymbolAddress((void**)&Vbh, g_Vbh);
    cudaGetSymbolAddress((void**)&Vbl, g_Vbl);

    minpos_kernel<<<1, 256>>>(pos, S_LEN);

    const int xn4 = (S_LEN * HID) / 4;
    const int wn4 = (HID * HID) / 4;
    conv_h_kernel<<<xn4 / 256, 256>>>(X, Xh, xn4);
    split_w_kernel<<<wn4 / 256, 256>>>(Wq, Wh + 0 * W_SZ, Wl + 0 * W_SZ, wn4);
    split_w_kernel<<<wn4 / 256, 256>>>(Wk, Wh + 1 * W_SZ, Wl + 1 * W_SZ, wn4);
    split_w_kernel<<<wn4 / 256, 256>>>(Wv, Wh + 2 * W_SZ, Wl + 2 * W_SZ, wn4);
    split_w_kernel<<<wn4 / 256, 256>>>(Wo, Wh + 3 * W_SZ, Wl + 3 * W_SZ, wn4);

    cudaFuncSetAttribute(gemm_qkv_kernel,
                         cudaFuncAttributeMaxDynamicSharedMemorySize, MT_SMEM);
    cudaFuncSetAttribute(gemm_mma_kernel,
                         cudaFuncAttributeMaxDynamicSharedMemorySize, MT_SMEM);

    // fused QKV: B has 6144 rows (Wq|Wk|Wv contiguous in g_Wh/g_Wl)
    dim3 gq(3 * HID / 128, S_LEN / 128);       // (48, 32)
    gemm_qkv_kernel<<<gq, 256, MT_SMEM>>>(Xh, Wh, Wl, Qp, Kp, Vbh, Vbl, HID);

    rope_split_kernel<<<S_LEN, 1024>>>(Qp, Kp, pos, Qbh, Kbh, Kbl);

    cudaFuncSetAttribute(attn_mma_kernel,
                         cudaFuncAttributeMaxDynamicSharedMemorySize, AT_SMEM);
    dim3 ag(S_LEN / 128, NHEAD);               // (32, 16)
    attn_mma_kernel<<<ag, 256, AT_SMEM>>>(Qbh, Kbh, Kbl, Vbh, Vbl, Aoh);

    dim3 gg(HID / 128, S_LEN / 128);           // (16, 32)
    gemm_mma_kernel<<<gg, 256, MT_SMEM>>>(Aoh, Wh + 3 * W_SZ, Wl + 3 * W_SZ,
                                          out, S_LEN, HID, HID);
}

// round 15
// speedup vs baseline: 4.4816x; 1.0096x over previous
#include <cuda_runtime.h>
#include <cuda_fp16.h>
#include <math.h>
#include <stdint.h>

#define S_LEN 4096
#define HID   2048
#define NHEAD 16
#define DHEAD 128
#define W_SZ  ((size_t)HID * HID)

// ---------------- scratch (device globals; no allocations allowed) ----------
__device__ float g_Q[(size_t)S_LEN * HID];
__device__ float g_K[(size_t)S_LEN * HID];
__device__ __align__(16) __half g_Xh[(size_t)S_LEN * HID];      // X fp16 (A-side single)
__device__ __align__(16) __half g_Wh[4 * W_SZ];                 // W hi (B-side)
__device__ __align__(16) __half g_Wl[4 * W_SZ];                 // W lo
__device__ __align__(16) __half g_Aoh[(size_t)S_LEN * HID];     // attn out fp16 single
__device__ __align__(16) __half g_Qbh[(size_t)S_LEN * HID];     // rope'd Q fp16 (scaled)
__device__ __align__(16) __half g_Kbh[(size_t)S_LEN * HID];     // rope'd K hi
__device__ __align__(16) __half g_Kbl[(size_t)S_LEN * HID];     // rope'd K lo
__device__ __align__(16) __half g_Vbh[(size_t)S_LEN * HID];     // V hi
__device__ __align__(16) __half g_Vbl[(size_t)S_LEN * HID];     // V lo
__device__ int g_minpos;

// ---------------- PTX helpers (all sm_80-era: valid on compute_103) ---------
__device__ __forceinline__ uint32_t smem_u32(const void* p) {
    uint32_t a;
    asm("{ .reg .u64 t; cvta.to.shared.u64 t, %1; cvt.u32.u64 %0, t; }"
        : "=r"(a) : "l"(p));
    return a;
}

__device__ __forceinline__ void cp16(uint32_t saddr, const void* g) {
    asm volatile("cp.async.cg.shared.global [%0], [%1], 16;"
                 :: "r"(saddr), "l"(g) : "memory");
}
__device__ __forceinline__ void cp_commit() {
    asm volatile("cp.async.commit_group;" ::: "memory");
}
template <int N>
__device__ __forceinline__ void cp_wait() {
    asm volatile("cp.async.wait_group %0;" :: "n"(N) : "memory");
}

#define LDSM_X4(r, addr) \
    asm volatile("ldmatrix.sync.aligned.m8n8.x4.shared.b16 {%0,%1,%2,%3}, [%4];" \
                 : "=r"((r)[0]), "=r"((r)[1]), "=r"((r)[2]), "=r"((r)[3]) \
                 : "r"(addr))

#define LDSM_X4T(r, addr) \
    asm volatile("ldmatrix.sync.aligned.m8n8.x4.trans.shared.b16 {%0,%1,%2,%3}, [%4];" \
                 : "=r"((r)[0]), "=r"((r)[1]), "=r"((r)[2]), "=r"((r)[3]) \
                 : "r"(addr))

__device__ __forceinline__ void mma_f16(float* c, const uint32_t* a,
                                        uint32_t b0, uint32_t b1) {
    asm volatile(
        "mma.sync.aligned.m16n8k16.row.col.f32.f16.f16.f32 "
        "{%0,%1,%2,%3}, {%4,%5,%6,%7}, {%8,%9}, {%0,%1,%2,%3};"
        : "+f"(c[0]), "+f"(c[1]), "+f"(c[2]), "+f"(c[3])
        : "r"(a[0]), "r"(a[1]), "r"(a[2]), "r"(a[3]), "r"(b0), "r"(b1));
}

__device__ __forceinline__ uint32_t swz(uint32_t boff) {   // SW128-style
    return boff ^ ((boff >> 3) & 0x70);
}

__device__ __forceinline__ uint32_t pack_h2(float x, float y) {
    __half2 h = __floats2half2_rn(x, y);
    return *reinterpret_cast<uint32_t*>(&h);
}

__device__ __forceinline__ void pack_hl_f16(float x, float y,
                                            uint32_t& h, uint32_t& l) {
    __half2 hh = __floats2half2_rn(x, y);
    h = *reinterpret_cast<uint32_t*>(&hh);
    __half2 ll = __floats2half2_rn(x - __low2float(hh), y - __high2float(hh));
    l = *reinterpret_cast<uint32_t*>(&ll);
}

__device__ __forceinline__ float ex2(float x) {
    float y;
    asm("ex2.approx.ftz.f32 %0, %1;" : "=f"(y) : "f"(x));
    return y;
}

// ---------------- min(position_ids)  (JAX demotes int64->int32) -------------
__global__ void minpos_kernel(const int* __restrict__ pos, int n)
{
    __shared__ int sm[256];
    int v = 0x7fffffff;
    for (int i = threadIdx.x; i < n; i += 256) {
        int p = pos[i];
        v = (p < v) ? p : v;
    }
    sm[threadIdx.x] = v;
    __syncthreads();
    for (int s = 128; s > 0; s >>= 1) {
        if (threadIdx.x < s) {
            int o = sm[threadIdx.x + s];
            if (o < sm[threadIdx.x]) sm[threadIdx.x] = o;
        }
        __syncthreads();
    }
    if (threadIdx.x == 0) g_minpos = sm[0];
}

// ---------------- fp32 -> fp16 conversions -----------------------------------
// all 4 weight matrices in one launch (hi/lo regions contiguous in g_Wh/g_Wl)
__global__ void split_w4_kernel(const float* __restrict__ W0,
                                const float* __restrict__ W1,
                                const float* __restrict__ W2,
                                const float* __restrict__ W3,
                                __half* __restrict__ hi,
                                __half* __restrict__ lo, int n4per)
{
    int i = blockIdx.x * blockDim.x + threadIdx.x;
    if (i >= 4 * n4per) return;
    int w = i / n4per;
    int j = i - w * n4per;
    const float* src = (w == 0) ? W0 : (w == 1) ? W1 : (w == 2) ? W2 : W3;
    float4 v = ((const float4*)src)[j];
    uint32_t h0, l0, h1, l1;
    pack_hl_f16(v.x, v.y, h0, l0);
    pack_hl_f16(v.z, v.w, h1, l1);
    ((uint2*)hi)[i] = make_uint2(h0, h1);
    ((uint2*)lo)[i] = make_uint2(l0, l1);
}

__global__ void conv_h_kernel(const float* __restrict__ x,
                              __half* __restrict__ h, int n4)
{
    int i = blockIdx.x * blockDim.x + threadIdx.x;
    if (i >= n4) return;
    float4 v = ((const float4*)x)[i];
    ((uint2*)h)[i] = make_uint2(pack_h2(v.x, v.y), pack_h2(v.z, v.w));
}

// ---------------- mma.sync fp16 2-pass GEMM core: C = A * B^T ---------------
// A fp16 single; B fp16 hi/lo. Tile 128x128, K chunks of 64. 8 warps (2m x 4n).
#define MT_TILE  16384                       // 128 rows x 64 fp16 (128B rows)
#define MT_STAGE (3 * MT_TILE)               // A, Bh, Bl = 48K
#define MT_SMEM  (2 * MT_STAGE)              // 98304 B

__device__ __forceinline__ void mt_prefetch(
    uint32_t st, const __half* A,
    const __half* Bh, const __half* Bl,
    int m0, int n0, int k0, int K, int tid)
{
#pragma unroll
    for (int i = 0; i < 4; ++i) {
        int idx = tid + i * 256;             // 0..1023
        int r   = idx >> 3;
        int s   = idx & 7;
        uint32_t sw = swz(r * 128 + s * 16);
        size_t ga = (size_t)(m0 + r) * K + k0 + s * 8;
        size_t gb = (size_t)(n0 + r) * K + k0 + s * 8;
        cp16(st + sw,               A  + ga);
        cp16(st + MT_TILE + sw,     Bh + gb);
        cp16(st + 2 * MT_TILE + sw, Bl + gb);
    }
    cp_commit();
}

__device__ __forceinline__ void mt_mainloop(
    float acc[4][4][4], uint32_t sbase,
    const __half* A, const __half* Bh, const __half* Bl,
    int m0, int n0, int K, int tid)
{
    const int wid  = tid >> 5;
    const int lane = tid & 31;
    const int wm   = wid & 1;
    const int wn   = wid >> 1;

    const int nch = K >> 6;
    mt_prefetch(sbase, A, Bh, Bl, m0, n0, 0, K, tid);

    for (int c = 0; c < nch; ++c) {
        if (c + 1 < nch) {
            mt_prefetch(sbase + ((c + 1) & 1) * MT_STAGE,
                        A, Bh, Bl, m0, n0, (c + 1) << 6, K, tid);
            cp_wait<1>();
        } else {
            cp_wait<0>();
        }
        __syncthreads();

        const uint32_t sA = sbase + (c & 1) * MT_STAGE;
        const uint32_t sB = sA + MT_TILE;

        const int a_row = wm * 64 + (lane & 15);
        const int a_sg  = lane >> 4;
        const int b_row = wn * 32 + ((lane >> 4) << 3) + (lane & 7);
        const int b_sg  = (lane >> 3) & 1;

#pragma unroll
        for (int ks = 0; ks < 4; ++ks) {
            uint32_t ah[4][4], bh[2][4], bl[2][4];
#pragma unroll
            for (int i = 0; i < 4; ++i) {
                uint32_t off = swz((a_row + i * 16) * 128 + (2 * ks + a_sg) * 16);
                LDSM_X4(ah[i], sA + off);
            }
#pragma unroll
            for (int jp = 0; jp < 2; ++jp) {
                uint32_t off = swz((b_row + jp * 16) * 128 + (2 * ks + b_sg) * 16);
                LDSM_X4(bh[jp], sB + off);
                LDSM_X4(bl[jp], sB + MT_TILE + off);
            }
#pragma unroll
            for (int i = 0; i < 4; ++i)
#pragma unroll
                for (int j = 0; j < 4; ++j) {
                    mma_f16(acc[i][j], ah[i],
                            bh[j >> 1][(j & 1) * 2], bh[j >> 1][(j & 1) * 2 + 1]);
                    mma_f16(acc[i][j], ah[i],
                            bl[j >> 1][(j & 1) * 2], bl[j >> 1][(j & 1) * 2 + 1]);
                }
        }
        __syncthreads();
    }
}

// Fused QKV GEMM: B = [Wq;Wk;Wv] (6144 rows). Q,K -> fp32; V -> fp16 hi/lo.
__global__ __launch_bounds__(256) void gemm_qkv_kernel(
    const __half* __restrict__ A,
    const __half* __restrict__ Bh, const __half* __restrict__ Bl,
    float* __restrict__ Qf, float* __restrict__ Kf,
    __half* __restrict__ Vh, __half* __restrict__ Vl, int K)
{
    extern __shared__ __align__(1024) char smc[];
    const uint32_t sbase = smem_u32(smc);
    const int tid  = threadIdx.x;
    const int wid  = tid >> 5;
    const int lane = tid & 31;
    const int m0 = blockIdx.y * 128;
    const int n0 = blockIdx.x * 128;

    float acc[4][4][4];
#pragma unroll
    for (int i = 0; i < 4; i++)
#pragma unroll
        for (int j = 0; j < 4; j++)
#pragma unroll
            for (int r = 0; r < 4; r++) acc[i][j][r] = 0.f;

    mt_mainloop(acc, sbase, A, Bh, Bl, m0, n0, K, tid);

    const int wm = wid & 1, wn = wid >> 1;
#pragma unroll
    for (int i = 0; i < 4; ++i) {
        int row = m0 + wm * 64 + i * 16 + (lane >> 2);
#pragma unroll
        for (int j = 0; j < 4; ++j) {
            int col = n0 + wn * 32 + j * 8 + (lane & 3) * 2;
            int cc  = col & 2047;
            size_t o0 = (size_t)row * HID + cc;
            size_t o1 = (size_t)(row + 8) * HID + cc;
            if (col < 4096) {
                float* dst = (col < 2048) ? Qf : Kf;
                *(float2*)(dst + o0) = make_float2(acc[i][j][0], acc[i][j][1]);
                *(float2*)(dst + o1) = make_float2(acc[i][j][2], acc[i][j][3]);
            } else {
                uint32_t h0, l0, h1, l1;
                pack_hl_f16(acc[i][j][0], acc[i][j][1], h0, l0);
                pack_hl_f16(acc[i][j][2], acc[i][j][3], h1, l1);
                *(uint32_t*)(Vh + o0) = h0; *(uint32_t*)(Vl + o0) = l0;
                *(uint32_t*)(Vh + o1) = h1; *(uint32_t*)(Vl + o1) = l1;
            }
        }
    }
}

// Plain GEMM (fp32 out): final Wo projection.
__global__ __launch_bounds__(256) void gemm_mma_kernel(
    const __half* __restrict__ A,
    const __half* __restrict__ Bh, const __half* __restrict__ Bl,
    float* __restrict__ C, int M, int N, int K)
{
    extern __shared__ __align__(1024) char smc[];
    const uint32_t sbase = smem_u32(smc);
    const int tid  = threadIdx.x;
    const int wid  = tid >> 5;
    const int lane = tid & 31;
    const int m0 = blockIdx.y * 128;
    const int n0 = blockIdx.x * 128;

    float acc[4][4][4];
#pragma unroll
    for (int i = 0; i < 4; i++)
#pragma unroll
        for (int j = 0; j < 4; j++)
#pragma unroll
            for (int r = 0; r < 4; r++) acc[i][j][r] = 0.f;

    mt_mainloop(acc, sbase, A, Bh, Bl, m0, n0, K, tid);

    const int wm = wid & 1, wn = wid >> 1;
#pragma unroll
    for (int i = 0; i < 4; ++i) {
        int row = m0 + wm * 64 + i * 16 + (lane >> 2);
#pragma unroll
        for (int j = 0; j < 4; ++j) {
            int col = n0 + wn * 32 + j * 8 + (lane & 3) * 2;
            *(float2*)(C + (size_t)row * N + col) =
                make_float2(acc[i][j][0], acc[i][j][1]);
            *(float2*)(C + (size_t)(row + 8) * N + col) =
                make_float2(acc[i][j][2], acc[i][j][3]);
        }
    }
}

// ---------------- RoPE + fp16 convert (Q scaled by scale*log2e; K hi/lo) ----
__global__ void rope_split_kernel(const float* __restrict__ Q,
                                  const float* __restrict__ K,
                                  const int* __restrict__ pos,
                                  __half* __restrict__ Qh,
                                  __half* __restrict__ Kh,
                                  __half* __restrict__ Kl)
{
    int s = blockIdx.x;
    int t = threadIdx.x;          // 1024 threads: (h, d<64)
    int h = t >> 6;
    int d = t & 63;

    const float QSC = (float)(0.08838834764831845 * 1.4426950408889634);

    float tp = (float)(pos[s] - g_minpos);
    float invf = (float)exp(-log(10000.0) * ((double)(2 * d) / 128.0));
    float ang = tp * invf;
    float c, sn;
    sincosf(ang, &sn, &c);

    size_t base = (size_t)s * HID + h * DHEAD;
    float q1 = Q[base + d], q2 = Q[base + d + 64];
    float k1 = K[base + d], k2 = K[base + d + 64];
    float qa = (q1 * c - q2 * sn) * QSC, qb = (q2 * c + q1 * sn) * QSC;
    float ka = k1 * c - k2 * sn, kb = k2 * c + k1 * sn;

    Qh[base + d]      = __float2half(qa);
    Qh[base + d + 64] = __float2half(qb);
    __half kh;
    kh = __float2half(ka); Kh[base + d] = kh;
    Kl[base + d]      = __float2half(ka - __half2float(kh));
    kh = __float2half(kb); Kh[base + d + 64] = kh;
    Kl[base + d + 64] = __float2half(kb - __half2float(kh));
}

// ---------------- tensor-core flash attention (fp16 2-pass, 2 CTAs/SM) -------
// CTA = 128 threads (4 warps x 16 q-rows), q-tile 64, k-block 32,
// K/V double-buffered. smem 80K -> 2 CTAs/SM: one CTA's HMMAs cover the
// other's softmax bubbles.
// smem: Q 16K @0 | K stages 2x16K @16K | V stages 2x16K @48K = 80K.
#define AT_SQ  0
#define AT_SK  16384
#define AT_SV  49152
#define AT_SMEM 81920

__device__ __forceinline__ void at_prefetch_kv(
    uint32_t sb, int stage, const __half* Kh, const __half* Kl,
    const __half* Vh, const __half* Vl,
    int k0, int h, int tid)
{
    const uint32_t sK = sb + AT_SK + stage * 16384;
    const uint32_t sV = sb + AT_SV + stage * 16384;
#pragma unroll
    for (int i = 0; i < 8; ++i) {             // K: 1024 cp16 (hi + lo)
        int idx = tid + i * 128;
        int hl = idx >> 9, rem = idx & 511;
        int r = rem >> 4, dc = rem & 15;
        uint32_t sa = sK + hl * 8192 + (dc >> 3) * 4096
                    + swz(r * 128 + (dc & 7) * 16);
        const __half* g = hl ? Kl : Kh;
        cp16(sa, g + (size_t)(k0 + r) * HID + h * DHEAD + dc * 8);
    }
#pragma unroll
    for (int i = 0; i < 8; ++i) {             // V: 1024 cp16 (hi + lo)
        int idx = tid + i * 128;
        int hl = idx >> 9, rem = idx & 511;
        int r = rem >> 4, dc = rem & 15;
        uint32_t sa = sV + hl * 8192 + (dc >> 3) * 4096
                    + swz(r * 128 + (dc & 7) * 16);
        const __half* g = hl ? Vl : Vh;
        cp16(sa, g + (size_t)(k0 + r) * HID + h * DHEAD + dc * 8);
    }
    cp_commit();
}

__global__ __launch_bounds__(128, 2) void attn_mma_kernel(
    const __half* __restrict__ Qh,
    const __half* __restrict__ Kh, const __half* __restrict__ Kl,
    const __half* __restrict__ Vh, const __half* __restrict__ Vl,
    __half* __restrict__ Oh)
{
    extern __shared__ __align__(1024) char smb[];
    const uint32_t sb = smem_u32(smb);
    const int tid  = threadIdx.x;
    const int wid  = tid >> 5;                          // 0..3
    const int lane = tid & 31;
    const int qb = (int)(gridDim.x - 1 - blockIdx.x);   // big blocks first
    const int h  = blockIdx.y;
    const int q0 = qb * 64;
    const int nkb = 2 * qb + 2;                         // k-blocks of 32
    const float MASKC = -1.4426950e9f;                  // -1e9 * log2(e)

    // Q tile (fp16 single, 64 rows): 1024 cp16, loaded once
#pragma unroll
    for (int i = 0; i < 8; ++i) {
        int idx = tid + i * 128;
        int r = idx >> 4, dc = idx & 15;
        uint32_t sa = sb + AT_SQ + (dc >> 3) * 8192
                    + swz(r * 128 + (dc & 7) * 16);
        cp16(sa, Qh + (size_t)(q0 + r) * HID + h * DHEAD + dc * 8);
    }
    at_prefetch_kv(sb, 0, Kh, Kl, Vh, Vl, 0, h, tid);   // commits Q + stage0

    float o[16][4];
#pragma unroll
    for (int t = 0; t < 16; ++t)
#pragma unroll
        for (int r = 0; r < 4; ++r) o[t][r] = 0.f;
    float m0r = -INFINITY, m1r = -INFINITY, l0r = 0.f, l1r = 0.f;

    const int qrow0 = q0 + wid * 16 + (lane >> 2);
    const int qrow1 = qrow0 + 8;

    for (int c = 0; c < nkb; ++c) {
        if (c + 1 < nkb) {
            at_prefetch_kv(sb, (c + 1) & 1, Kh, Kl, Vh, Vl, (c + 1) * 32, h, tid);
            cp_wait<1>();
        } else {
            cp_wait<0>();
        }
        __syncthreads();

        const uint32_t sK = sb + AT_SK + (c & 1) * 16384;
        const uint32_t sV = sb + AT_SV + (c & 1) * 16384;
        const int k0 = c * 32;

        // ---- S = Q K^T  (64x32; 2 passes: Q*Kh + Q*Kl) ----
        float sacc[4][4];
#pragma unroll
        for (int j = 0; j < 4; ++j)
#pragma unroll
            for (int r = 0; r < 4; ++r) sacc[j][r] = 0.f;

#pragma unroll
        for (int ks = 0; ks < 8; ++ks) {
            const int kh = ks >> 2, sg = ks & 3;
            uint32_t a[4];
            uint32_t qoff = kh * 8192 +
                swz((wid * 16 + (lane & 15)) * 128 + (2 * sg + (lane >> 4)) * 16);
            LDSM_X4(a, sb + AT_SQ + qoff);
#pragma unroll
            for (int ng = 0; ng < 2; ++ng) {
                uint32_t bh[4], bl[4];
                uint32_t koff = kh * 4096 +
                    swz((ng * 16 + ((lane >> 4) << 3) + (lane & 7)) * 128 +
                        (2 * sg + ((lane >> 3) & 1)) * 16);
                LDSM_X4(bh, sK + koff);
                LDSM_X4(bl, sK + 8192 + koff);
                mma_f16(sacc[2 * ng],     a, bh[0], bh[1]);
                mma_f16(sacc[2 * ng],     a, bl[0], bl[1]);
                mma_f16(sacc[2 * ng + 1], a, bh[2], bh[3]);
                mma_f16(sacc[2 * ng + 1], a, bl[2], bl[3]);
            }
        }

        // ---- causal mask (diagonal blocks only) + online softmax in exp2 ----
        if ((k0 + 31) > q0) {
#pragma unroll
            for (int j = 0; j < 4; ++j) {
                int col = k0 + j * 8 + (lane & 3) * 2;
                if (col     > qrow0) sacc[j][0] += MASKC;
                if (col + 1 > qrow0) sacc[j][1] += MASKC;
                if (col     > qrow1) sacc[j][2] += MASKC;
                if (col + 1 > qrow1) sacc[j][3] += MASKC;
            }
        }
        float mx0 = -INFINITY, mx1 = -INFINITY;
#pragma unroll
        for (int j = 0; j < 4; ++j) {
            mx0 = fmaxf(mx0, fmaxf(sacc[j][0], sacc[j][1]));
            mx1 = fmaxf(mx1, fmaxf(sacc[j][2], sacc[j][3]));
        }
        mx0 = fmaxf(mx0, __shfl_xor_sync(0xffffffffu, mx0, 1));
        mx0 = fmaxf(mx0, __shfl_xor_sync(0xffffffffu, mx0, 2));
        mx1 = fmaxf(mx1, __shfl_xor_sync(0xffffffffu, mx1, 1));
        mx1 = fmaxf(mx1, __shfl_xor_sync(0xffffffffu, mx1, 2));

        float mn0 = fmaxf(m0r, mx0), mn1 = fmaxf(m1r, mx1);
        float fac0 = ex2(m0r - mn0), fac1 = ex2(m1r - mn1);
        m0r = mn0; m1r = mn1;

        float ls0 = 0.f, ls1 = 0.f;
#pragma unroll
        for (int j = 0; j < 4; ++j) {
            sacc[j][0] = ex2(sacc[j][0] - mn0);
            sacc[j][1] = ex2(sacc[j][1] - mn0);
            sacc[j][2] = ex2(sacc[j][2] - mn1);
            sacc[j][3] = ex2(sacc[j][3] - mn1);
            ls0 += sacc[j][0] + sacc[j][1];
            ls1 += sacc[j][2] + sacc[j][3];
        }
        ls0 += __shfl_xor_sync(0xffffffffu, ls0, 1);
        ls0 += __shfl_xor_sync(0xffffffffu, ls0, 2);
        ls1 += __shfl_xor_sync(0xffffffffu, ls1, 1);
        ls1 += __shfl_xor_sync(0xffffffffu, ls1, 2);
        l0r = l0r * fac0 + ls0;
        l1r = l1r * fac1 + ls1;

#pragma unroll
        for (int t = 0; t < 16; ++t) {
            o[t][0] *= fac0; o[t][1] *= fac0;
            o[t][2] *= fac1; o[t][3] *= fac1;
        }

        // ---- O += P V  (P fp16 single; 2 passes: P*Vh + P*Vl) ----
#pragma unroll
        for (int ks = 0; ks < 2; ++ks) {
            uint32_t p[4];
            p[0] = pack_h2(sacc[2 * ks][0],     sacc[2 * ks][1]);
            p[1] = pack_h2(sacc[2 * ks][2],     sacc[2 * ks][3]);
            p[2] = pack_h2(sacc[2 * ks + 1][0], sacc[2 * ks + 1][1]);
            p[3] = pack_h2(sacc[2 * ks + 1][2], sacc[2 * ks + 1][3]);
#pragma unroll
            for (int ng = 0; ng < 8; ++ng) {
                uint32_t vh[4], vl[4];
                uint32_t voff = (ng >> 2) * 4096 +
                    swz((ks * 16 + (lane & 15)) * 128 +
                        (ng & 3) * 32 + (lane >> 4) * 16);
                LDSM_X4T(vh, sV + voff);
                LDSM_X4T(vl, sV + 8192 + voff);
                mma_f16(o[2 * ng],     p, vh[0], vh[1]);
                mma_f16(o[2 * ng],     p, vl[0], vl[1]);
                mma_f16(o[2 * ng + 1], p, vh[2], vh[3]);
                mma_f16(o[2 * ng + 1], p, vl[2], vl[3]);
            }
        }
        __syncthreads();
    }

    // ---- normalize + write fp16 single (feeds Wo GEMM A-side) ----
    float inv0 = 1.f / l0r, inv1 = 1.f / l1r;
#pragma unroll
    for (int t = 0; t < 16; ++t) {
        size_t col = h * DHEAD + t * 8 + (lane & 3) * 2;
        *(uint32_t*)(Oh + (size_t)qrow0 * HID + col) =
            pack_h2(o[t][0] * inv0, o[t][1] * inv0);
        *(uint32_t*)(Oh + (size_t)qrow1 * HID + col) =
            pack_h2(o[t][2] * inv1, o[t][3] * inv1);
    }
}

// ---------------- launch ----------------------------------------------------
extern "C" void kernel_launch(void* const* d_in, const int* in_sizes, int n_in,
                              void* d_out, int out_size)
{
    const float* X    = (const float*)d_in[0];
    const int*   pos  = (const int*)d_in[2];   // JAX x64 disabled: int32
    const float* Wq   = (const float*)d_in[3];
    const float* Wk   = (const float*)d_in[4];
    const float* Wv   = (const float*)d_in[5];
    const float* Wo   = (const float*)d_in[6];
    float*       out  = (float*)d_out;

    float *Qp, *Kp;
    __half *Xh, *Wh, *Wl, *Aoh, *Qbh, *Kbh, *Kbl, *Vbh, *Vbl;
    cudaGetSymbolAddress((void**)&Qp, g_Q);
    cudaGetSymbolAddress((void**)&Kp, g_K);
    cudaGetSymbolAddress((void**)&Xh, g_Xh);
    cudaGetSymbolAddress((void**)&Wh, g_Wh);
    cudaGetSymbolAddress((void**)&Wl, g_Wl);
    cudaGetSymbolAddress((void**)&Aoh, g_Aoh);
    cudaGetSymbolAddress((void**)&Qbh, g_Qbh);
    cudaGetSymbolAddress((void**)&Kbh, g_Kbh);
    cudaGetSymbolAddress((void**)&Kbl, g_Kbl);
    cudaGetSymbolAddress((void**)&Vbh, g_Vbh);
    cudaGetSymbolAddress((void**)&Vbl, g_Vbl);

    minpos_kernel<<<1, 256>>>(pos, S_LEN);

    const int xn4 = (S_LEN * HID) / 4;
    const int wn4 = (HID * HID) / 4;
    conv_h_kernel<<<xn4 / 256, 256>>>(X, Xh, xn4);
    split_w4_kernel<<<(4 * wn4) / 256, 256>>>(Wq, Wk, Wv, Wo, Wh, Wl, wn4);

    cudaFuncSetAttribute(gemm_qkv_kernel,
                         cudaFuncAttributeMaxDynamicSharedMemorySize, MT_SMEM);
    cudaFuncSetAttribute(gemm_mma_kernel,
                         cudaFuncAttributeMaxDynamicSharedMemorySize, MT_SMEM);

    // fused QKV: B has 6144 rows (Wq|Wk|Wv contiguous in g_Wh/g_Wl)
    dim3 gq(3 * HID / 128, S_LEN / 128);       // (48, 32)
    gemm_qkv_kernel<<<gq, 256, MT_SMEM>>>(Xh, Wh, Wl, Qp, Kp, Vbh, Vbl, HID);

    rope_split_kernel<<<S_LEN, 1024>>>(Qp, Kp, pos, Qbh, Kbh, Kbl);

    cudaFuncSetAttribute(attn_mma_kernel,
                         cudaFuncAttributeMaxDynamicSharedMemorySize, AT_SMEM);
    dim3 ag(S_LEN / 64, NHEAD);                // (64, 16)
    attn_mma_kernel<<<ag, 128, AT_SMEM>>>(Qbh, Kbh, Kbl, Vbh, Vbl, Aoh);

    dim3 gg(HID / 128, S_LEN / 128);           // (16, 32)
    gemm_mma_kernel<<<gg, 256, MT_SMEM>>>(Aoh, Wh + 3 * W_SZ, Wl + 3 * W_SZ,
                                          out, S_LEN, HID, HID);
}

// round 16
// speedup vs baseline: 4.9040x; 1.0943x over previous
#include <cuda_runtime.h>
#include <cuda_fp16.h>
#include <math.h>
#include <stdint.h>

#define S_LEN 4096
#define HID   2048
#define NHEAD 16
#define DHEAD 128
#define W_SZ  ((size_t)HID * HID)

// ---------------- scratch (device globals; no allocations allowed) ----------
__device__ float g_Q[(size_t)S_LEN * HID];
__device__ float g_K[(size_t)S_LEN * HID];
__device__ __align__(16) __half g_Xh[(size_t)S_LEN * HID];      // X fp16 (A-side single)
__device__ __align__(16) __half g_Wh[4 * W_SZ];                 // W hi (B-side)
__device__ __align__(16) __half g_Wl[4 * W_SZ];                 // W lo
__device__ __align__(16) __half g_Aoh[(size_t)S_LEN * HID];     // attn out fp16 single
__device__ __align__(16) __half g_Qbh[(size_t)S_LEN * HID];     // rope'd Q fp16 (scaled)
__device__ __align__(16) __half g_Kbh[(size_t)S_LEN * HID];     // rope'd K hi
__device__ __align__(16) __half g_Kbl[(size_t)S_LEN * HID];     // rope'd K lo
__device__ __align__(16) __half g_Vbh[(size_t)S_LEN * HID];     // V fp16 (single)
__device__ int g_minpos;

// ---------------- PTX helpers (all sm_80-era: valid on compute_103) ---------
__device__ __forceinline__ uint32_t smem_u32(const void* p) {
    uint32_t a;
    asm("{ .reg .u64 t; cvta.to.shared.u64 t, %1; cvt.u32.u64 %0, t; }"
        : "=r"(a) : "l"(p));
    return a;
}

__device__ __forceinline__ void cp16(uint32_t saddr, const void* g) {
    asm volatile("cp.async.cg.shared.global [%0], [%1], 16;"
                 :: "r"(saddr), "l"(g) : "memory");
}
__device__ __forceinline__ void cp_commit() {
    asm volatile("cp.async.commit_group;" ::: "memory");
}
template <int N>
__device__ __forceinline__ void cp_wait() {
    asm volatile("cp.async.wait_group %0;" :: "n"(N) : "memory");
}

#define LDSM_X4(r, addr) \
    asm volatile("ldmatrix.sync.aligned.m8n8.x4.shared.b16 {%0,%1,%2,%3}, [%4];" \
                 : "=r"((r)[0]), "=r"((r)[1]), "=r"((r)[2]), "=r"((r)[3]) \
                 : "r"(addr))

#define LDSM_X4T(r, addr) \
    asm volatile("ldmatrix.sync.aligned.m8n8.x4.trans.shared.b16 {%0,%1,%2,%3}, [%4];" \
                 : "=r"((r)[0]), "=r"((r)[1]), "=r"((r)[2]), "=r"((r)[3]) \
                 : "r"(addr))

__device__ __forceinline__ void mma_f16(float* c, const uint32_t* a,
                                        uint32_t b0, uint32_t b1) {
    asm volatile(
        "mma.sync.aligned.m16n8k16.row.col.f32.f16.f16.f32 "
        "{%0,%1,%2,%3}, {%4,%5,%6,%7}, {%8,%9}, {%0,%1,%2,%3};"
        : "+f"(c[0]), "+f"(c[1]), "+f"(c[2]), "+f"(c[3])
        : "r"(a[0]), "r"(a[1]), "r"(a[2]), "r"(a[3]), "r"(b0), "r"(b1));
}

__device__ __forceinline__ uint32_t swz(uint32_t boff) {   // SW128-style
    return boff ^ ((boff >> 3) & 0x70);
}

__device__ __forceinline__ uint32_t pack_h2(float x, float y) {
    __half2 h = __floats2half2_rn(x, y);
    return *reinterpret_cast<uint32_t*>(&h);
}

__device__ __forceinline__ void pack_hl_f16(float x, float y,
                                            uint32_t& h, uint32_t& l) {
    __half2 hh = __floats2half2_rn(x, y);
    h = *reinterpret_cast<uint32_t*>(&hh);
    __half2 ll = __floats2half2_rn(x - __low2float(hh), y - __high2float(hh));
    l = *reinterpret_cast<uint32_t*>(&ll);
}

__device__ __forceinline__ float ex2(float x) {
    float y;
    asm("ex2.approx.ftz.f32 %0, %1;" : "=f"(y) : "f"(x));
    return y;
}

// ---------------- min(position_ids)  (JAX demotes int64->int32) -------------
__global__ void minpos_kernel(const int* __restrict__ pos, int n)
{
    __shared__ int sm[256];
    int v = 0x7fffffff;
    for (int i = threadIdx.x; i < n; i += 256) {
        int p = pos[i];
        v = (p < v) ? p : v;
    }
    sm[threadIdx.x] = v;
    __syncthreads();
    for (int s = 128; s > 0; s >>= 1) {
        if (threadIdx.x < s) {
            int o = sm[threadIdx.x + s];
            if (o < sm[threadIdx.x]) sm[threadIdx.x] = o;
        }
        __syncthreads();
    }
    if (threadIdx.x == 0) g_minpos = sm[0];
}

// ---------------- fp32 -> fp16 conversions -----------------------------------
__global__ void split_w4_kernel(const float* __restrict__ W0,
                                const float* __restrict__ W1,
                                const float* __restrict__ W2,
                                const float* __restrict__ W3,
                                __half* __restrict__ hi,
                                __half* __restrict__ lo, int n4per)
{
    int i = blockIdx.x * blockDim.x + threadIdx.x;
    if (i >= 4 * n4per) return;
    int w = i / n4per;
    int j = i - w * n4per;
    const float* src = (w == 0) ? W0 : (w == 1) ? W1 : (w == 2) ? W2 : W3;
    float4 v = ((const float4*)src)[j];
    uint32_t h0, l0, h1, l1;
    pack_hl_f16(v.x, v.y, h0, l0);
    pack_hl_f16(v.z, v.w, h1, l1);
    ((uint2*)hi)[i] = make_uint2(h0, h1);
    ((uint2*)lo)[i] = make_uint2(l0, l1);
}

__global__ void conv_h_kernel(const float* __restrict__ x,
                              __half* __restrict__ h, int n4)
{
    int i = blockIdx.x * blockDim.x + threadIdx.x;
    if (i >= n4) return;
    float4 v = ((const float4*)x)[i];
    ((uint2*)h)[i] = make_uint2(pack_h2(v.x, v.y), pack_h2(v.z, v.w));
}

// ---------------- mma.sync fp16 2-pass GEMM core: C = A * B^T ---------------
// A fp16 single; B fp16 hi/lo. Tile 128x128, K chunks of 64, 3-stage pipeline.
#define MT_TILE  16384                       // 128 rows x 64 fp16 (128B rows)
#define MT_STAGE (3 * MT_TILE)               // A, Bh, Bl = 48K
#define MT_SMEM  (3 * MT_STAGE)              // 147456 B (3 stages)

__device__ __forceinline__ void mt_prefetch(
    uint32_t st, const __half* A,
    const __half* Bh, const __half* Bl,
    int m0, int n0, int k0, int K, int tid)
{
#pragma unroll
    for (int i = 0; i < 4; ++i) {
        int idx = tid + i * 256;             // 0..1023
        int r   = idx >> 3;
        int s   = idx & 7;
        uint32_t sw = swz(r * 128 + s * 16);
        size_t ga = (size_t)(m0 + r) * K + k0 + s * 8;
        size_t gb = (size_t)(n0 + r) * K + k0 + s * 8;
        cp16(st + sw,               A  + ga);
        cp16(st + MT_TILE + sw,     Bh + gb);
        cp16(st + 2 * MT_TILE + sw, Bl + gb);
    }
    cp_commit();
}

__device__ __forceinline__ void mt_mainloop(
    float acc[4][4][4], uint32_t sbase,
    const __half* A, const __half* Bh, const __half* Bl,
    int m0, int n0, int K, int tid)
{
    const int wid  = tid >> 5;
    const int lane = tid & 31;
    const int wm   = wid & 1;
    const int wn   = wid >> 1;

    const int nch = K >> 6;
    mt_prefetch(sbase, A, Bh, Bl, m0, n0, 0, K, tid);
    mt_prefetch(sbase + MT_STAGE, A, Bh, Bl, m0, n0, 64, K, tid);

    for (int c = 0; c < nch; ++c) {
        if (c + 2 < nch) {
            mt_prefetch(sbase + ((c + 2) % 3) * MT_STAGE,
                        A, Bh, Bl, m0, n0, (c + 2) << 6, K, tid);
            cp_wait<2>();
        } else if (c + 1 < nch) {
            cp_wait<1>();
        } else {
            cp_wait<0>();
        }
        __syncthreads();

        const uint32_t sA = sbase + (c % 3) * MT_STAGE;
        const uint32_t sB = sA + MT_TILE;

        const int a_row = wm * 64 + (lane & 15);
        const int a_sg  = lane >> 4;
        const int b_row = wn * 32 + ((lane >> 4) << 3) + (lane & 7);
        const int b_sg  = (lane >> 3) & 1;

#pragma unroll
        for (int ks = 0; ks < 4; ++ks) {
            uint32_t ah[4][4], bh[2][4], bl[2][4];
#pragma unroll
            for (int i = 0; i < 4; ++i) {
                uint32_t off = swz((a_row + i * 16) * 128 + (2 * ks + a_sg) * 16);
                LDSM_X4(ah[i], sA + off);
            }
#pragma unroll
            for (int jp = 0; jp < 2; ++jp) {
                uint32_t off = swz((b_row + jp * 16) * 128 + (2 * ks + b_sg) * 16);
                LDSM_X4(bh[jp], sB + off);
                LDSM_X4(bl[jp], sB + MT_TILE + off);
            }
#pragma unroll
            for (int i = 0; i < 4; ++i)
#pragma unroll
                for (int j = 0; j < 4; ++j) {
                    mma_f16(acc[i][j], ah[i],
                            bh[j >> 1][(j & 1) * 2], bh[j >> 1][(j & 1) * 2 + 1]);
                    mma_f16(acc[i][j], ah[i],
                            bl[j >> 1][(j & 1) * 2], bl[j >> 1][(j & 1) * 2 + 1]);
                }
        }
        __syncthreads();
    }
}

// Fused QKV GEMM: B = [Wq;Wk;Wv] (6144 rows). Q,K -> fp32; V -> fp16 single.
__global__ __launch_bounds__(256) void gemm_qkv_kernel(
    const __half* __restrict__ A,
    const __half* __restrict__ Bh, const __half* __restrict__ Bl,
    float* __restrict__ Qf, float* __restrict__ Kf,
    __half* __restrict__ Vh, int K)
{
    extern __shared__ __align__(1024) char smc[];
    const uint32_t sbase = smem_u32(smc);
    const int tid  = threadIdx.x;
    const int wid  = tid >> 5;
    const int lane = tid & 31;
    const int m0 = blockIdx.y * 128;
    const int n0 = blockIdx.x * 128;

    float acc[4][4][4];
#pragma unroll
    for (int i = 0; i < 4; i++)
#pragma unroll
        for (int j = 0; j < 4; j++)
#pragma unroll
            for (int r = 0; r < 4; r++) acc[i][j][r] = 0.f;

    mt_mainloop(acc, sbase, A, Bh, Bl, m0, n0, K, tid);

    const int wm = wid & 1, wn = wid >> 1;
#pragma unroll
    for (int i = 0; i < 4; ++i) {
        int row = m0 + wm * 64 + i * 16 + (lane >> 2);
#pragma unroll
        for (int j = 0; j < 4; ++j) {
            int col = n0 + wn * 32 + j * 8 + (lane & 3) * 2;
            int cc  = col & 2047;
            size_t o0 = (size_t)row * HID + cc;
            size_t o1 = (size_t)(row + 8) * HID + cc;
            if (col < 4096) {
                float* dst = (col < 2048) ? Qf : Kf;
                *(float2*)(dst + o0) = make_float2(acc[i][j][0], acc[i][j][1]);
                *(float2*)(dst + o1) = make_float2(acc[i][j][2], acc[i][j][3]);
            } else {
                *(uint32_t*)(Vh + o0) = pack_h2(acc[i][j][0], acc[i][j][1]);
                *(uint32_t*)(Vh + o1) = pack_h2(acc[i][j][2], acc[i][j][3]);
            }
        }
    }
}

// Plain GEMM (fp32 out): final Wo projection.
__global__ __launch_bounds__(256) void gemm_mma_kernel(
    const __half* __restrict__ A,
    const __half* __restrict__ Bh, const __half* __restrict__ Bl,
    float* __restrict__ C, int M, int N, int K)
{
    extern __shared__ __align__(1024) char smc[];
    const uint32_t sbase = smem_u32(smc);
    const int tid  = threadIdx.x;
    const int wid  = tid >> 5;
    const int lane = tid & 31;
    const int m0 = blockIdx.y * 128;
    const int n0 = blockIdx.x * 128;

    float acc[4][4][4];
#pragma unroll
    for (int i = 0; i < 4; i++)
#pragma unroll
        for (int j = 0; j < 4; j++)
#pragma unroll
            for (int r = 0; r < 4; r++) acc[i][j][r] = 0.f;

    mt_mainloop(acc, sbase, A, Bh, Bl, m0, n0, K, tid);

    const int wm = wid & 1, wn = wid >> 1;
#pragma unroll
    for (int i = 0; i < 4; ++i) {
        int row = m0 + wm * 64 + i * 16 + (lane >> 2);
#pragma unroll
        for (int j = 0; j < 4; ++j) {
            int col = n0 + wn * 32 + j * 8 + (lane & 3) * 2;
            *(float2*)(C + (size_t)row * N + col) =
                make_float2(acc[i][j][0], acc[i][j][1]);
            *(float2*)(C + (size_t)(row + 8) * N + col) =
                make_float2(acc[i][j][2], acc[i][j][3]);
        }
    }
}

// ---------------- RoPE + fp16 convert (Q scaled by scale*log2e; K hi/lo) ----
__global__ void rope_split_kernel(const float* __restrict__ Q,
                                  const float* __restrict__ K,
                                  const int* __restrict__ pos,
                                  __half* __restrict__ Qh,
                                  __half* __restrict__ Kh,
                                  __half* __restrict__ Kl)
{
    int s = blockIdx.x;
    int t = threadIdx.x;          // 1024 threads: (h, d<64)
    int h = t >> 6;
    int d = t & 63;

    const float QSC = (float)(0.08838834764831845 * 1.4426950408889634);

    float tp = (float)(pos[s] - g_minpos);
    float invf = (float)exp(-log(10000.0) * ((double)(2 * d) / 128.0));
    float ang = tp * invf;
    float c, sn;
    sincosf(ang, &sn, &c);

    size_t base = (size_t)s * HID + h * DHEAD;
    float q1 = Q[base + d], q2 = Q[base + d + 64];
    float k1 = K[base + d], k2 = K[base + d + 64];
    float qa = (q1 * c - q2 * sn) * QSC, qb = (q2 * c + q1 * sn) * QSC;
    float ka = k1 * c - k2 * sn, kb = k2 * c + k1 * sn;

    Qh[base + d]      = __float2half(qa);
    Qh[base + d + 64] = __float2half(qb);
    __half kh;
    kh = __float2half(ka); Kh[base + d] = kh;
    Kl[base + d]      = __float2half(ka - __half2float(kh));
    kh = __float2half(kb); Kh[base + d + 64] = kh;
    Kl[base + d + 64] = __float2half(kb - __half2float(kh));
}

// ---------------- tensor-core flash attention --------------------------------
// CTA = 128 threads (4 warps x 16 q-rows), q-tile 64, k-block 64,
// K hi/lo 2-pass, V SINGLE fp16 1-pass. smem 112K -> 2 CTAs/SM: co-resident
// CTA's HMMAs cover softmax bubbles, softmax cadence back to per-64-cols.
// smem: Q 16K @0 | K stages 2x32K @16K | V stages 2x16K @80K = 114688 B.
#define AT_SQ  0
#define AT_SK  16384
#define AT_SV  81920
#define AT_SMEM 114688

__device__ __forceinline__ void at_prefetch_kv(
    uint32_t sb, int stage, const __half* Kh, const __half* Kl,
    const __half* Vh, int k0, int h, int tid)
{
    const uint32_t sK = sb + AT_SK + stage * 32768;
    const uint32_t sV = sb + AT_SV + stage * 16384;
#pragma unroll
    for (int i = 0; i < 16; ++i) {            // K: 2048 cp16 (hi + lo)
        int idx = tid + i * 128;
        int hl = idx >> 10, rem = idx & 1023;
        int r = rem >> 4, dc = rem & 15;
        uint32_t sa = sK + hl * 16384 + (dc >> 3) * 8192
                    + swz(r * 128 + (dc & 7) * 16);
        const __half* g = hl ? Kl : Kh;
        cp16(sa, g + (size_t)(k0 + r) * HID + h * DHEAD + dc * 8);
    }
#pragma unroll
    for (int i = 0; i < 8; ++i) {             // V: 1024 cp16 (single)
        int idx = tid + i * 128;
        int r = idx >> 4, dc = idx & 15;
        uint32_t sa = sV + (dc >> 3) * 8192 + swz(r * 128 + (dc & 7) * 16);
        cp16(sa, Vh + (size_t)(k0 + r) * HID + h * DHEAD + dc * 8);
    }
    cp_commit();
}

__global__ __launch_bounds__(128, 2) void attn_mma_kernel(
    const __half* __restrict__ Qh,
    const __half* __restrict__ Kh, const __half* __restrict__ Kl,
    const __half* __restrict__ Vh,
    __half* __restrict__ Oh)
{
    extern __shared__ __align__(1024) char smb[];
    const uint32_t sb = smem_u32(smb);
    const int tid  = threadIdx.x;
    const int wid  = tid >> 5;                          // 0..3
    const int lane = tid & 31;
    const int qb = (int)(gridDim.x - 1 - blockIdx.x);   // big blocks first
    const int h  = blockIdx.y;
    const int q0 = qb * 64;
    const int nkb = qb + 1;                             // k-blocks of 64
    const float MASKC = -1.4426950e9f;                  // -1e9 * log2(e)

    // Q tile (fp16 single, 64 rows): 1024 cp16, loaded once
#pragma unroll
    for (int i = 0; i < 8; ++i) {
        int idx = tid + i * 128;
        int r = idx >> 4, dc = idx & 15;
        uint32_t sa = sb + AT_SQ + (dc >> 3) * 8192
                    + swz(r * 128 + (dc & 7) * 16);
        cp16(sa, Qh + (size_t)(q0 + r) * HID + h * DHEAD + dc * 8);
    }
    at_prefetch_kv(sb, 0, Kh, Kl, Vh, 0, h, tid);       // commits Q + stage0

    float o[16][4];
#pragma unroll
    for (int t = 0; t < 16; ++t)
#pragma unroll
        for (int r = 0; r < 4; ++r) o[t][r] = 0.f;
    float m0r = -INFINITY, m1r = -INFINITY, l0r = 0.f, l1r = 0.f;

    const int qrow0 = q0 + wid * 16 + (lane >> 2);
    const int qrow1 = qrow0 + 8;

    for (int c = 0; c < nkb; ++c) {
        if (c + 1 < nkb) {
            at_prefetch_kv(sb, (c + 1) & 1, Kh, Kl, Vh, (c + 1) * 64, h, tid);
            cp_wait<1>();
        } else {
            cp_wait<0>();
        }
        __syncthreads();

        const uint32_t sK = sb + AT_SK + (c & 1) * 32768;
        const uint32_t sV = sb + AT_SV + (c & 1) * 16384;
        const int k0 = c * 64;

        // ---- S = Q K^T  (64x64; 2 passes: Q*Kh + Q*Kl) ----
        float sacc[8][4];
#pragma unroll
        for (int j = 0; j < 8; ++j)
#pragma unroll
            for (int r = 0; r < 4; ++r) sacc[j][r] = 0.f;

#pragma unroll
        for (int ks = 0; ks < 8; ++ks) {
            const int kh = ks >> 2, sg = ks & 3;
            uint32_t a[4];
            uint32_t qoff = kh * 8192 +
                swz((wid * 16 + (lane & 15)) * 128 + (2 * sg + (lane >> 4)) * 16);
            LDSM_X4(a, sb + AT_SQ + qoff);
#pragma unroll
            for (int ng = 0; ng < 4; ++ng) {
                uint32_t bh[4], bl[4];
                uint32_t koff = kh * 8192 +
                    swz((ng * 16 + ((lane >> 4) << 3) + (lane & 7)) * 128 +
                        (2 * sg + ((lane >> 3) & 1)) * 16);
                LDSM_X4(bh, sK + koff);
                LDSM_X4(bl, sK + 16384 + koff);
                mma_f16(sacc[2 * ng],     a, bh[0], bh[1]);
                mma_f16(sacc[2 * ng],     a, bl[0], bl[1]);
                mma_f16(sacc[2 * ng + 1], a, bh[2], bh[3]);
                mma_f16(sacc[2 * ng + 1], a, bl[2], bl[3]);
            }
        }

        // ---- causal mask (diagonal block only) + online softmax in exp2 ----
        if ((k0 + 63) > q0) {
#pragma unroll
            for (int j = 0; j < 8; ++j) {
                int col = k0 + j * 8 + (lane & 3) * 2;
                if (col     > qrow0) sacc[j][0] += MASKC;
                if (col + 1 > qrow0) sacc[j][1] += MASKC;
                if (col     > qrow1) sacc[j][2] += MASKC;
                if (col + 1 > qrow1) sacc[j][3] += MASKC;
            }
        }
        float mx0 = -INFINITY, mx1 = -INFINITY;
#pragma unroll
        for (int j = 0; j < 8; ++j) {
            mx0 = fmaxf(mx0, fmaxf(sacc[j][0], sacc[j][1]));
            mx1 = fmaxf(mx1, fmaxf(sacc[j][2], sacc[j][3]));
        }
        mx0 = fmaxf(mx0, __shfl_xor_sync(0xffffffffu, mx0, 1));
        mx0 = fmaxf(mx0, __shfl_xor_sync(0xffffffffu, mx0, 2));
        mx1 = fmaxf(mx1, __shfl_xor_sync(0xffffffffu, mx1, 1));
        mx1 = fmaxf(mx1, __shfl_xor_sync(0xffffffffu, mx1, 2));

        float mn0 = fmaxf(m0r, mx0), mn1 = fmaxf(m1r, mx1);
        float fac0 = ex2(m0r - mn0), fac1 = ex2(m1r - mn1);
        m0r = mn0; m1r = mn1;

        float ls0 = 0.f, ls1 = 0.f;
#pragma unroll
        for (int j = 0; j < 8; ++j) {
            sacc[j][0] = ex2(sacc[j][0] - mn0);
            sacc[j][1] = ex2(sacc[j][1] - mn0);
            sacc[j][2] = ex2(sacc[j][2] - mn1);
            sacc[j][3] = ex2(sacc[j][3] - mn1);
            ls0 += sacc[j][0] + sacc[j][1];
            ls1 += sacc[j][2] + sacc[j][3];
        }
        ls0 += __shfl_xor_sync(0xffffffffu, ls0, 1);
        ls0 += __shfl_xor_sync(0xffffffffu, ls0, 2);
        ls1 += __shfl_xor_sync(0xffffffffu, ls1, 1);
        ls1 += __shfl_xor_sync(0xffffffffu, ls1, 2);
        l0r = l0r * fac0 + ls0;
        l1r = l1r * fac1 + ls1;

#pragma unroll
        for (int t = 0; t < 16; ++t) {
            o[t][0] *= fac0; o[t][1] *= fac0;
            o[t][2] *= fac1; o[t][3] *= fac1;
        }

        // ---- O += P V  (P fp16 single; V fp16 single: 1 pass) ----
#pragma unroll
        for (int ks = 0; ks < 4; ++ks) {
            uint32_t p[4];
            p[0] = pack_h2(sacc[2 * ks][0],     sacc[2 * ks][1]);
            p[1] = pack_h2(sacc[2 * ks][2],     sacc[2 * ks][3]);
            p[2] = pack_h2(sacc[2 * ks + 1][0], sacc[2 * ks + 1][1]);
            p[3] = pack_h2(sacc[2 * ks + 1][2], sacc[2 * ks + 1][3]);
#pragma unroll
            for (int ng = 0; ng < 8; ++ng) {
                uint32_t vh[4];
                uint32_t voff = (ng >> 2) * 8192 +
                    swz((ks * 16 + (lane & 15)) * 128 +
                        (ng & 3) * 32 + (lane >> 4) * 16);
                LDSM_X4T(vh, sV + voff);
                mma_f16(o[2 * ng],     p, vh[0], vh[1]);
                mma_f16(o[2 * ng + 1], p, vh[2], vh[3]);
            }
        }
        __syncthreads();
    }

    // ---- normalize + write fp16 single (feeds Wo GEMM A-side) ----
    float inv0 = 1.f / l0r, inv1 = 1.f / l1r;
#pragma unroll
    for (int t = 0; t < 16; ++t) {
        size_t col = h * DHEAD + t * 8 + (lane & 3) * 2;
        *(uint32_t*)(Oh + (size_t)qrow0 * HID + col) =
            pack_h2(o[t][0] * inv0, o[t][1] * inv0);
        *(uint32_t*)(Oh + (size_t)qrow1 * HID + col) =
            pack_h2(o[t][2] * inv1, o[t][3] * inv1);
    }
}

// ---------------- launch ----------------------------------------------------
extern "C" void kernel_launch(void* const* d_in, const int* in_sizes, int n_in,
                              void* d_out, int out_size)
{
    const float* X    = (const float*)d_in[0];
    const int*   pos  = (const int*)d_in[2];   // JAX x64 disabled: int32
    const float* Wq   = (const float*)d_in[3];
    const float* Wk   = (const float*)d_in[4];
    const float* Wv   = (const float*)d_in[5];
    const float* Wo   = (const float*)d_in[6];
    float*       out  = (float*)d_out;

    float *Qp, *Kp;
    __half *Xh, *Wh, *Wl, *Aoh, *Qbh, *Kbh, *Kbl, *Vbh;
    cudaGetSymbolAddress((void**)&Qp, g_Q);
    cudaGetSymbolAddress((void**)&Kp, g_K);
    cudaGetSymbolAddress((void**)&Xh, g_Xh);
    cudaGetSymbolAddress((void**)&Wh, g_Wh);
    cudaGetSymbolAddress((void**)&Wl, g_Wl);
    cudaGetSymbolAddress((void**)&Aoh, g_Aoh);
    cudaGetSymbolAddress((void**)&Qbh, g_Qbh);
    cudaGetSymbolAddress((void**)&Kbh, g_Kbh);
    cudaGetSymbolAddress((void**)&Kbl, g_Kbl);
    cudaGetSymbolAddress((void**)&Vbh, g_Vbh);

    minpos_kernel<<<1, 256>>>(pos, S_LEN);

    const int xn4 = (S_LEN * HID) / 4;
    const int wn4 = (HID * HID) / 4;
    conv_h_kernel<<<xn4 / 256, 256>>>(X, Xh, xn4);
    split_w4_kernel<<<(4 * wn4) / 256, 256>>>(Wq, Wk, Wv, Wo, Wh, Wl, wn4);

    cudaFuncSetAttribute(gemm_qkv_kernel,
                         cudaFuncAttributeMaxDynamicSharedMemorySize, MT_SMEM);
    cudaFuncSetAttribute(gemm_mma_kernel,
                         cudaFuncAttributeMaxDynamicSharedMemorySize, MT_SMEM);

    // fused QKV: B has 6144 rows (Wq|Wk|Wv contiguous in g_Wh/g_Wl)
    dim3 gq(3 * HID / 128, S_LEN / 128);       // (48, 32)
    gemm_qkv_kernel<<<gq, 256, MT_SMEM>>>(Xh, Wh, Wl, Qp, Kp, Vbh, HID);

    rope_split_kernel<<<S_LEN, 1024>>>(Qp, Kp, pos, Qbh, Kbh, Kbl);

    cudaFuncSetAttribute(attn_mma_kernel,
                         cudaFuncAttributeMaxDynamicSharedMemorySize, AT_SMEM);
    dim3 ag(S_LEN / 64, NHEAD);                // (64, 16)
    attn_mma_kernel<<<ag, 128, AT_SMEM>>>(Qbh, Kbh, Kbl, Vbh, Aoh);

    dim3 gg(HID / 128, S_LEN / 128);           // (16, 32)
    gemm_mma_kernel<<<gg, 256, MT_SMEM>>>(Aoh, Wh + 3 * W_SZ, Wl + 3 * W_SZ,
                                          out, S_LEN, HID, HID);
}